// round 7
// baseline (speedup 1.0000x reference)
#include <cuda_runtime.h>
#include <cuda_bf16.h>
#include <cuda_fp16.h>
#include <cstdint>
#include <math.h>

// Problem dims (fixed by the dataset)
#define BB 4
#define NN 4096
#define DD 1024
#define HH 16
#define DH 64
#define FF 4096
#define MM (BB * NN)          // 16384
#define TOT ((size_t)MM * DD) // 16,777,216

// ===================== helpers =====================
__device__ __forceinline__ uint32_t smem_u32(const void* p) {
    uint32_t a;
    asm("{ .reg .u64 t; cvta.to.shared.u64 t, %1; cvt.u32.u64 %0, t; }" : "=r"(a) : "l"(p));
    return a;
}
__device__ __forceinline__ void cp_async16(uint32_t dst, const void* src) {
    asm volatile("cp.async.cg.shared.global [%0], [%1], 16;"
                 :: "r"(dst), "l"(__cvta_generic_to_global(src)));
}
__device__ __forceinline__ void cp_commit() { asm volatile("cp.async.commit_group;" ::: "memory"); }
__device__ __forceinline__ void cp_wait0()  { asm volatile("cp.async.wait_group 0;" ::: "memory"); }
__device__ __forceinline__ void cp_wait1()  { asm volatile("cp.async.wait_group 1;" ::: "memory"); }

#define MMA16816(d, a, b0, b1) \
    asm volatile("mma.sync.aligned.m16n8k16.row.col.f32.bf16.bf16.f32 " \
        "{%0,%1,%2,%3}, {%4,%5,%6,%7}, {%8,%9}, {%0,%1,%2,%3};" \
        : "+f"((d)[0]), "+f"((d)[1]), "+f"((d)[2]), "+f"((d)[3]) \
        : "r"((a)[0]), "r"((a)[1]), "r"((a)[2]), "r"((a)[3]), "r"(b0), "r"(b1))

#define MMAF16(d, a, b0, b1) \
    asm volatile("mma.sync.aligned.m16n8k16.row.col.f32.f16.f16.f32 " \
        "{%0,%1,%2,%3}, {%4,%5,%6,%7}, {%8,%9}, {%0,%1,%2,%3};" \
        : "+f"((d)[0]), "+f"((d)[1]), "+f"((d)[2]), "+f"((d)[3]) \
        : "r"((a)[0]), "r"((a)[1]), "r"((a)[2]), "r"((a)[3]), "r"(b0), "r"(b1))

#define LDMX4(r, addr) \
    asm volatile("ldmatrix.sync.aligned.m8n8.x4.shared.b16 {%0,%1,%2,%3}, [%4];" \
        : "=r"((r)[0]), "=r"((r)[1]), "=r"((r)[2]), "=r"((r)[3]) : "r"(addr))

// ===================== scratch (static device globals) =====================
__device__ float g_attn[MM * DD];
__device__ float g_out1[MM * DD];
__device__ float g_G[BB * HH * DH * DH];
__device__ float g_Wt[BB * HH * DH * DH];
__device__ float g_WqC[BB * DD * DD];
__device__ float g_s[BB * DD];
__device__ float g_rq[BB * DD];
__device__ float g_rk[BB * DD];
__device__ float g_cvec[BB * DD];
__device__ float g_zero[DD];          // never written: stays 0
__device__ double g_part[4096][2];
__device__ double g_red[2];

__device__ __nv_bfloat16 g_xhi[MM * DD],  g_xlo[MM * DD];
__device__ __nv_bfloat16 g_xThi[(size_t)DD * MM], g_xTlo[(size_t)DD * MM];
__device__ __nv_bfloat16 g_Chi[BB * DD * DD],  g_Clo[BB * DD * DD];
__device__ __nv_bfloat16 g_WoMhi[BB * DD * DD], g_WoMlo[BB * DD * DD];
__device__ __nv_bfloat16 g_Ehi[BB * DD * DD],  g_Elo[BB * DD * DD];
__device__ __nv_bfloat16 g_wqhi[DD * DD], g_wqlo[DD * DD];
__device__ __nv_bfloat16 g_wvThi[DD * DD], g_wvTlo[DD * DD];

// fp16 MLP path
__device__ __half g_w1f[FF * DD];
__device__ __half g_w2f[DD * FF];
__device__ __half g_atf[MM * DD];
__device__ __half g_hf[(size_t)MM * FF];

// ===================== fp32 -> bf16 hi/lo split =====================
__global__ void __launch_bounds__(256) split_kernel(
    const float* __restrict__ src, __nv_bfloat16* __restrict__ hi,
    __nv_bfloat16* __restrict__ lo, size_t n4)
{
    const size_t stride = (size_t)gridDim.x * blockDim.x;
    for (size_t i4 = (size_t)blockIdx.x * blockDim.x + threadIdx.x; i4 < n4; i4 += stride) {
        float4 v = ((const float4*)src)[i4];
        __nv_bfloat16 h0 = __float2bfloat16(v.x);
        __nv_bfloat16 h1 = __float2bfloat16(v.y);
        __nv_bfloat16 h2 = __float2bfloat16(v.z);
        __nv_bfloat16 h3 = __float2bfloat16(v.w);
        __nv_bfloat162 hA; hA.x = h0; hA.y = h1;
        __nv_bfloat162 hB; hB.x = h2; hB.y = h3;
        __nv_bfloat162 lA; lA.x = __float2bfloat16(v.x - __bfloat162float(h0));
                           lA.y = __float2bfloat16(v.y - __bfloat162float(h1));
        __nv_bfloat162 lB; lB.x = __float2bfloat16(v.z - __bfloat162float(h2));
                           lB.y = __float2bfloat16(v.w - __bfloat162float(h3));
        ((__nv_bfloat162*)hi)[i4 * 2 + 0] = hA;
        ((__nv_bfloat162*)hi)[i4 * 2 + 1] = hB;
        ((__nv_bfloat162*)lo)[i4 * 2 + 0] = lA;
        ((__nv_bfloat162*)lo)[i4 * 2 + 1] = lB;
    }
}

// transposed split: src [R][C] fp32 -> hi/lo [C][R] bf16
__global__ void __launch_bounds__(256) splitT_kernel(
    const float* __restrict__ src, __nv_bfloat16* __restrict__ hi,
    __nv_bfloat16* __restrict__ lo, int R, int C)
{
    __shared__ float t[32][33];
    const int c0 = blockIdx.x * 32, r0 = blockIdx.y * 32;
    const int tx = threadIdx.x & 31, ty = threadIdx.x >> 5; // 32 x 8
    for (int rr = ty; rr < 32; rr += 8)
        t[rr][tx] = src[(size_t)(r0 + rr) * C + c0 + tx];
    __syncthreads();
    for (int cc = ty; cc < 32; cc += 8) {
        const float v = t[tx][cc];
        const __nv_bfloat16 h = __float2bfloat16(v);
        const size_t o = (size_t)(c0 + cc) * R + r0 + tx;
        hi[o] = h;
        lo[o] = __float2bfloat16(v - __bfloat162float(h));
    }
}

// ===================== fp32 -> fp16 convert =====================
__global__ void __launch_bounds__(256) cvtf16_kernel(
    const float* __restrict__ src, __half* __restrict__ dst, size_t n4)
{
    const size_t stride = (size_t)gridDim.x * blockDim.x;
    for (size_t i4 = (size_t)blockIdx.x * blockDim.x + threadIdx.x; i4 < n4; i4 += stride) {
        float4 v = ((const float4*)src)[i4];
        ((__half2*)dst)[i4 * 2 + 0] = __floats2half2_rn(v.x, v.y);
        ((__half2*)dst)[i4 * 2 + 1] = __floats2half2_rn(v.z, v.w);
    }
}

// ===================== bf16 hi/lo HMMA GEMM (3 products), batched/strided =====================
#define GW_BM 128
#define GW_BN 128
#define GW_BK 32
#define ROWB 80
#define BUFB (128 * ROWB)
#define STAGEB (4 * BUFB)
#define GW_SMEM (2 * STAGEB)       // 81920

// C[z][m,n] = sum_k A[z][m,k] * W[z][n,k] + bias[z][n] (+res)
template <bool HAS_RES, int OUTMODE, bool SYMSKIP> // OUTMODE 0: fp32; 1: bf16 hi/lo
__global__ void __launch_bounds__(256, 2) gemm_mma(
    const __nv_bfloat16* __restrict__ Ahi, const __nv_bfloat16* __restrict__ Alo,
    const __nv_bfloat16* __restrict__ Whi, const __nv_bfloat16* __restrict__ Wlo,
    const float* __restrict__ bias, const float* __restrict__ res,
    float* __restrict__ Cf, __nv_bfloat16* __restrict__ Chi, __nv_bfloat16* __restrict__ Clo,
    int K, int lda, int ldw, int ldc,
    long long saA, long long saW, long long saC, int saBias)
{
    if (SYMSKIP && (int)blockIdx.x < (int)blockIdx.y) return;
    extern __shared__ char sm[];
    const int z = blockIdx.z;
    Ahi += (size_t)z * saA;  Alo += (size_t)z * saA;
    Whi += (size_t)z * saW;  Wlo += (size_t)z * saW;
    bias += (size_t)z * saBias;
    if (HAS_RES) res += (size_t)z * saC;
    if (OUTMODE == 0) Cf += (size_t)z * saC;
    else { Chi += (size_t)z * saC; Clo += (size_t)z * saC; }

    const int tid = threadIdx.x;
    const int wid = tid >> 5;
    const int lane = tid & 31;
    const int wm = wid & 3;
    const int wn = wid >> 2;
    const int bm = blockIdx.y * GW_BM;
    const int bn = blockIdx.x * GW_BN;
    const int KT = K / GW_BK;
    const uint32_t smb = smem_u32(sm);

    auto load_stage = [&](int kt, uint32_t sb) {
        const int k0 = kt * GW_BK;
#pragma unroll
        for (int i = 0; i < 8; i++) {
            const int c = tid + i * 256;
            const int buf = c >> 9;           // 0:Ahi 1:Alo 2:Whi 3:Wlo
            const int cc = c & 511;
            const int row = cc >> 2;
            const int qq = cc & 3;
            const __nv_bfloat16* gb = (buf == 0) ? Ahi : (buf == 1) ? Alo
                                     : (buf == 2) ? Whi : Wlo;
            const int ld = (buf < 2) ? lda : ldw;
            const int grow = ((buf < 2) ? bm : bn) + row;
            const void* src = gb + (size_t)grow * ld + k0 + qq * 8;
            cp_async16(sb + buf * BUFB + row * ROWB + qq * 16, src);
        }
    };

    float acc[2][8][4];
#pragma unroll
    for (int mt = 0; mt < 2; mt++)
#pragma unroll
        for (int nt = 0; nt < 8; nt++)
#pragma unroll
            for (int r = 0; r < 4; r++) acc[mt][nt][r] = 0.0f;

    load_stage(0, smb);
    cp_commit();

    const int lr = lane & 7;
    const int a_row = wm * 32 + lr + ((lane & 8) ? 8 : 0);
    const int a_kb  = (lane & 16) ? 16 : 0;
    const int b_row = wn * 64 + lr + ((lane & 16) ? 8 : 0);
    const int b_kb  = (lane & 8) ? 16 : 0;

    for (int kt = 0; kt < KT; kt++) {
        const uint32_t sb = smb + (uint32_t)(kt & 1) * STAGEB;
        if (kt + 1 < KT) {
            load_stage(kt + 1, smb + (uint32_t)((kt + 1) & 1) * STAGEB);
            cp_commit();
            cp_wait1();
        } else {
            cp_wait0();
        }
        __syncthreads();

        const uint32_t As = sb;
        const uint32_t Bs = sb + 2 * BUFB;

#pragma unroll
        for (int k16 = 0; k16 < 2; k16++) {
            const int kc = k16 * 32;
            uint32_t ah[2][4], al[2][4];
#pragma unroll
            for (int mt = 0; mt < 2; mt++) {
                const uint32_t aAddr = As + (uint32_t)((a_row + mt * 16) * ROWB + kc + a_kb);
                LDMX4(ah[mt], aAddr);
                LDMX4(al[mt], aAddr + BUFB);
            }
#pragma unroll
            for (int p = 0; p < 4; p++) {
                uint32_t bh[4], bl[4];
                const uint32_t bAddr = Bs + (uint32_t)((b_row + p * 16) * ROWB + kc + b_kb);
                LDMX4(bh, bAddr);
                LDMX4(bl, bAddr + BUFB);
#pragma unroll
                for (int sub = 0; sub < 2; sub++) {
                    const int nt = p * 2 + sub;
                    const uint32_t b0h = bh[sub * 2], b1h = bh[sub * 2 + 1];
                    const uint32_t b0l = bl[sub * 2], b1l = bl[sub * 2 + 1];
#pragma unroll
                    for (int mt = 0; mt < 2; mt++) {
                        MMA16816(acc[mt][nt], ah[mt], b0h, b1h);
                        MMA16816(acc[mt][nt], ah[mt], b0l, b1l);
                        MMA16816(acc[mt][nt], al[mt], b0h, b1h);
                    }
                }
            }
        }
        __syncthreads();
    }

#pragma unroll
    for (int mt = 0; mt < 2; mt++) {
        const int r0 = bm + wm * 32 + mt * 16 + (lane >> 2);
#pragma unroll
        for (int nt = 0; nt < 8; nt++) {
            const int c = bn + wn * 64 + nt * 8 + ((lane & 3) << 1);
            const float b0 = bias[c], b1 = bias[c + 1];
#pragma unroll
            for (int half = 0; half < 2; half++) {
                const int row = r0 + half * 8;
                float v0 = acc[mt][nt][half * 2 + 0] + b0;
                float v1 = acc[mt][nt][half * 2 + 1] + b1;
                if (HAS_RES) {
                    const float2 rr = *(const float2*)(res + (size_t)row * ldc + c);
                    v0 += rr.x; v1 += rr.y;
                }
                if (OUTMODE == 0) {
                    float2 o; o.x = v0; o.y = v1;
                    *(float2*)(Cf + (size_t)row * ldc + c) = o;
                } else {
                    __nv_bfloat162 h, l;
                    h.x = __float2bfloat16(v0);
                    h.y = __float2bfloat16(v1);
                    l.x = __float2bfloat16(v0 - __bfloat162float(h.x));
                    l.y = __float2bfloat16(v1 - __bfloat162float(h.y));
                    *(__nv_bfloat162*)(Chi + (size_t)row * ldc + c) = h;
                    *(__nv_bfloat162*)(Clo + (size_t)row * ldc + c) = l;
                }
            }
        }
    }
}

// mirror strictly-lower blocks of symmetric C (hi/lo) from the computed upper blocks
__global__ void __launch_bounds__(256) mirror_kernel(
    __nv_bfloat16* __restrict__ hi, __nv_bfloat16* __restrict__ lo)
{
    const size_t zoff = (size_t)blockIdx.y * DD * DD;
    const int base = blockIdx.x * 1024 + threadIdx.x * 4;
#pragma unroll
    for (int m = 0; m < 4; m++) {
        const int e = base + m;
        const int r = e >> 10, c = e & 1023;
        if ((c >> 7) < (r >> 7)) {
            hi[zoff + (size_t)r * DD + c] = hi[zoff + (size_t)c * DD + r];
            lo[zoff + (size_t)r * DD + c] = lo[zoff + (size_t)c * DD + r];
        }
    }
}

// ===================== fp16 single-product HMMA GEMM (MLP path) =====================
#define F16_STAGEB (2 * BUFB)
#define F16_SMEM (2 * F16_STAGEB)

template <bool HAS_RES, bool GELU, bool OUTF16>
__global__ void __launch_bounds__(256, 2) gemm_f16(
    const __half* __restrict__ A, const __half* __restrict__ B,
    const float* __restrict__ bias, const float* __restrict__ res,
    float* __restrict__ Cf, __half* __restrict__ Ch,
    int M, int N, int K)
{
    extern __shared__ char sm[];
    const int tid = threadIdx.x;
    const int wid = tid >> 5;
    const int lane = tid & 31;
    const int wm = wid & 3;
    const int wn = wid >> 2;
    const int bm = blockIdx.y * GW_BM;
    const int bn = blockIdx.x * GW_BN;
    const int KT = K / GW_BK;
    const uint32_t smb = smem_u32(sm);

    auto load_stage = [&](int kt, uint32_t sb) {
        const int k0 = kt * GW_BK;
#pragma unroll
        for (int i = 0; i < 4; i++) {
            const int c = tid + i * 256;
            const int buf = c >> 9;
            const int cc = c & 511;
            const int row = cc >> 2;
            const int qq = cc & 3;
            const __half* gb = buf ? B : A;
            const int grow = (buf ? bn : bm) + row;
            const void* src = gb + (size_t)grow * K + k0 + qq * 8;
            cp_async16(sb + buf * BUFB + row * ROWB + qq * 16, src);
        }
    };

    float acc[2][8][4];
#pragma unroll
    for (int mt = 0; mt < 2; mt++)
#pragma unroll
        for (int nt = 0; nt < 8; nt++)
#pragma unroll
            for (int r = 0; r < 4; r++) acc[mt][nt][r] = 0.0f;

    load_stage(0, smb);
    cp_commit();

    const int lr = lane & 7;
    const int a_row = wm * 32 + lr + ((lane & 8) ? 8 : 0);
    const int a_kb  = (lane & 16) ? 16 : 0;
    const int b_row = wn * 64 + lr + ((lane & 16) ? 8 : 0);
    const int b_kb  = (lane & 8) ? 16 : 0;

    for (int kt = 0; kt < KT; kt++) {
        const uint32_t sb = smb + (uint32_t)(kt & 1) * F16_STAGEB;
        if (kt + 1 < KT) {
            load_stage(kt + 1, smb + (uint32_t)((kt + 1) & 1) * F16_STAGEB);
            cp_commit();
            cp_wait1();
        } else {
            cp_wait0();
        }
        __syncthreads();

        const uint32_t As = sb;
        const uint32_t Bs = sb + BUFB;

#pragma unroll
        for (int k16 = 0; k16 < 2; k16++) {
            const int kc = k16 * 32;
            uint32_t af[2][4];
#pragma unroll
            for (int mt = 0; mt < 2; mt++)
                LDMX4(af[mt], As + (uint32_t)((a_row + mt * 16) * ROWB + kc + a_kb));
#pragma unroll
            for (int p = 0; p < 4; p++) {
                uint32_t bf[4];
                LDMX4(bf, Bs + (uint32_t)((b_row + p * 16) * ROWB + kc + b_kb));
#pragma unroll
                for (int sub = 0; sub < 2; sub++) {
                    const int nt = p * 2 + sub;
#pragma unroll
                    for (int mt = 0; mt < 2; mt++)
                        MMAF16(acc[mt][nt], af[mt], bf[sub * 2], bf[sub * 2 + 1]);
                }
            }
        }
        __syncthreads();
    }

#pragma unroll
    for (int mt = 0; mt < 2; mt++) {
        const int r0 = bm + wm * 32 + mt * 16 + (lane >> 2);
#pragma unroll
        for (int nt = 0; nt < 8; nt++) {
            const int c = bn + wn * 64 + nt * 8 + ((lane & 3) << 1);
            const float b0 = bias[c], b1 = bias[c + 1];
#pragma unroll
            for (int half = 0; half < 2; half++) {
                const int row = r0 + half * 8;
                float v0 = acc[mt][nt][half * 2 + 0] + b0;
                float v1 = acc[mt][nt][half * 2 + 1] + b1;
                if (HAS_RES) {
                    const float2 rr = *(const float2*)(res + (size_t)row * N + c);
                    v0 += rr.x; v1 += rr.y;
                }
                if (GELU) {
                    v0 = 0.5f * v0 * (1.0f + erff(v0 * 0.70710678118654752f));
                    v1 = 0.5f * v1 * (1.0f + erff(v1 * 0.70710678118654752f));
                }
                if (OUTF16) {
                    *(__half2*)(Ch + (size_t)row * N + c) = __floats2half2_rn(v0, v1);
                } else {
                    float2 o; o.x = v0; o.y = v1;
                    *(float2*)(Cf + (size_t)row * N + c) = o;
                }
            }
        }
    }
}

// ===================== attention algebra small kernels =====================
// s[b][d] = sum_n x[b,n,d]
__global__ void __launch_bounds__(256) sums_kernel(const float* __restrict__ x, float* __restrict__ s)
{
    const int b = blockIdx.x;
    const int d = blockIdx.y * 256 + threadIdx.x;
    const float* p = x + ((size_t)b * NN) * DD + d;
    float acc = 0.0f;
    for (int n = 0; n < NN; n++) acc += p[(size_t)n * DD];
    s[b * DD + d] = acc;
}

// rq[b] = Wq s_b ; rk[b] = Wk s_b
__global__ void __launch_bounds__(128) rqrk_kernel(
    const float* __restrict__ wq, const float* __restrict__ wk,
    const float* __restrict__ s, float* __restrict__ rq, float* __restrict__ rk)
{
    const int b = blockIdx.x;
    const int o = blockIdx.y * 128 + threadIdx.x;
    const float* sb = s + b * DD;
    float aq = 0.0f, ak = 0.0f;
    const float* pq = wq + (size_t)o * DD;
    const float* pk = wk + (size_t)o * DD;
    for (int d = 0; d < DD; d++) { aq += pq[d] * sb[d]; ak += pk[d] * sb[d]; }
    rq[b * DD + o] = aq;
    rk[b * DD + o] = ak;
}

// G[bh][i][j] = sum_d WqC_b[h*64+i, d]*Wk[h*64+j, d]  + rank-1 bias terms
__global__ void __launch_bounds__(256) G_kernel(
    const float* __restrict__ WqC, const float* __restrict__ wk,
    const float* __restrict__ bq, const float* __restrict__ bk,
    const float* __restrict__ rq, const float* __restrict__ rk,
    float* __restrict__ G)
{
    const int bh = blockIdx.x;
    const int b = bh >> 4, h = bh & 15;
    const int tid = threadIdx.x;
    __shared__ float As[DH][33];
    __shared__ float Bs[DH][33];

    float acc[4][4];
#pragma unroll
    for (int i = 0; i < 4; i++)
#pragma unroll
        for (int j = 0; j < 4; j++) acc[i][j] = 0.0f;

    const int ty = tid >> 4, tx = tid & 15;
    const int lrow = tid >> 2;          // 0..63
    const int lcol = (tid & 3) * 8;     // 0,8,16,24

    for (int d0 = 0; d0 < DD; d0 += 32) {
        const float* pA = WqC + (size_t)b * DD * DD + (size_t)(h * DH + lrow) * DD + d0 + lcol;
        const float* pB = wk + (size_t)(h * DH + lrow) * DD + d0 + lcol;
        // float4 global loads, SCALAR shared stores (odd pitch 33 is not 16B-aligned)
        float4 a0 = *(const float4*)pA, a1 = *(const float4*)(pA + 4);
        float4 b0 = *(const float4*)pB, b1 = *(const float4*)(pB + 4);
        As[lrow][lcol + 0] = a0.x; As[lrow][lcol + 1] = a0.y;
        As[lrow][lcol + 2] = a0.z; As[lrow][lcol + 3] = a0.w;
        As[lrow][lcol + 4] = a1.x; As[lrow][lcol + 5] = a1.y;
        As[lrow][lcol + 6] = a1.z; As[lrow][lcol + 7] = a1.w;
        Bs[lrow][lcol + 0] = b0.x; Bs[lrow][lcol + 1] = b0.y;
        Bs[lrow][lcol + 2] = b0.z; Bs[lrow][lcol + 3] = b0.w;
        Bs[lrow][lcol + 4] = b1.x; Bs[lrow][lcol + 5] = b1.y;
        Bs[lrow][lcol + 6] = b1.z; Bs[lrow][lcol + 7] = b1.w;
        __syncthreads();
#pragma unroll
        for (int dd = 0; dd < 32; dd++) {
            float qr[4], br[4];
#pragma unroll
            for (int i = 0; i < 4; i++) qr[i] = As[ty * 4 + i][dd];
#pragma unroll
            for (int j = 0; j < 4; j++) br[j] = Bs[tx * 4 + j][dd];
#pragma unroll
            for (int i = 0; i < 4; i++)
#pragma unroll
                for (int j = 0; j < 4; j++) acc[i][j] += qr[i] * br[j];
        }
        __syncthreads();
    }

#pragma unroll
    for (int i = 0; i < 4; i++) {
        const int gi = h * DH + ty * 4 + i;
#pragma unroll
        for (int j = 0; j < 4; j++) {
            const int gj = h * DH + tx * 4 + j;
            float v = acc[i][j]
                    + bq[gi] * rk[b * DD + gj]
                    + rq[b * DD + gi] * bk[gj]
                    + (float)NN * bq[gi] * bk[gj];
            G[(size_t)bh * (DH * DH) + (ty * 4 + i) * DH + tx * 4 + j] = v;
        }
    }
}

// weights[bh][i][j] = | DFT64 over k of G[bh][i][k] at freq j |
__global__ void __launch_bounds__(256) weights_kernel(
    const float* __restrict__ G, float* __restrict__ Wt)
{
    const int bh = blockIdx.x;
    const int tid = threadIdx.x;
    __shared__ float Gs[DH][DH];
    __shared__ float ct[DH], st[DH];

    for (int e = tid; e < DH * DH; e += 256)
        Gs[e >> 6][e & 63] = G[(size_t)bh * (DH * DH) + e];
    if (tid < DH) {
        float a = 6.283185307179586f * (float)tid / 64.0f;
        ct[tid] = cosf(a);
        st[tid] = sinf(a);
    }
    __syncthreads();

    const int i = tid >> 2;
    const int j0 = (tid & 3) * 16;
    for (int jj = 0; jj < 16; jj++) {
        const int j = j0 + jj;
        float re = 0.0f, im = 0.0f;
#pragma unroll
        for (int kk = 0; kk < DH; kk++) {
            const int t = (kk * j) & 63;
            const float g = Gs[i][kk];
            re += g * ct[t];
            im += g * st[t];
        }
        Wt[(size_t)bh * (DH * DH) + i * DH + j] = sqrtf(re * re + im * im);
    }
}

// (Wo M_b)[o, h*64+j] = sum_i Wo[o, h*64+i] * Wt[b*16+h][i][j]  -> bf16 hi/lo
__global__ void __launch_bounds__(256) wom_kernel(
    const float* __restrict__ wo, const float* __restrict__ Wt,
    __nv_bfloat16* __restrict__ WoMhi, __nv_bfloat16* __restrict__ WoMlo)
{
    const int ot = blockIdx.x, h = blockIdx.y, b = blockIdx.z;
    const int tid = threadIdx.x;
    __shared__ float Os[DH][DH + 1];
    __shared__ float Ms[DH][DH + 1];

    const int lrow = tid >> 2;
    const int lcol = (tid & 3) * 16;
#pragma unroll
    for (int q = 0; q < 4; q++) {
        // float4 global loads, SCALAR shared stores (odd pitch 65 is not 16B-aligned)
        float4 ov = *(const float4*)(wo + (size_t)(ot * DH + lrow) * DD + h * DH + lcol + q * 4);
        float4 mv4 = *(const float4*)(Wt + (size_t)(b * HH + h) * (DH * DH) + lrow * DH + lcol + q * 4);
        Os[lrow][lcol + q * 4 + 0] = ov.x;  Os[lrow][lcol + q * 4 + 1] = ov.y;
        Os[lrow][lcol + q * 4 + 2] = ov.z;  Os[lrow][lcol + q * 4 + 3] = ov.w;
        Ms[lrow][lcol + q * 4 + 0] = mv4.x; Ms[lrow][lcol + q * 4 + 1] = mv4.y;
        Ms[lrow][lcol + q * 4 + 2] = mv4.z; Ms[lrow][lcol + q * 4 + 3] = mv4.w;
    }
    __syncthreads();

    const int ty = tid >> 4, tx = tid & 15;
#pragma unroll
    for (int oo = 0; oo < 4; oo++) {
        const int o = ty * 4 + oo;
        float vr[4] = {0.f, 0.f, 0.f, 0.f};
        for (int i = 0; i < DH; i++) {
            const float a = Os[o][i];
#pragma unroll
            for (int jj = 0; jj < 4; jj++) vr[jj] += a * Ms[i][tx * 4 + jj];
        }
#pragma unroll
        for (int jj = 0; jj < 4; jj++) {
            const size_t idx = (size_t)b * DD * DD + (size_t)(ot * DH + o) * DD + h * DH + tx * 4 + jj;
            const __nv_bfloat16 hv = __float2bfloat16(vr[jj]);
            WoMhi[idx] = hv;
            WoMlo[idx] = __float2bfloat16(vr[jj] - __bfloat162float(hv));
        }
    }
}

// c_b = Wo (M_b bv) + bo
__global__ void __launch_bounds__(256) mvc_kernel(
    const float* __restrict__ Wt, const float* __restrict__ bv,
    const float* __restrict__ wo, const float* __restrict__ bo,
    float* __restrict__ cvec)
{
    const int b = blockIdx.x;
    const int tid = threadIdx.x;
    __shared__ float mv[DD];
    for (int f = tid; f < DD; f += 256) {
        const int h = f >> 6, i = f & 63;
        float sacc = 0.0f;
        const float* wrow = Wt + (size_t)(b * HH + h) * (DH * DH) + i * DH;
        for (int j = 0; j < DH; j++) sacc += wrow[j] * bv[h * DH + j];
        mv[f] = sacc;
    }
    __syncthreads();
    for (int o = tid; o < DD; o += 256) {
        float sacc = 0.0f;
        const float* wrow = wo + (size_t)o * DD;
        for (int f = 0; f < DD; f++) sacc += wrow[f] * mv[f];
        cvec[b * DD + o] = sacc + bo[o];
    }
}

// ===================== global-std reduction + norm =====================
__global__ void __launch_bounds__(256) red1_kernel(const float* __restrict__ x, size_t n)
{
    float s = 0.0f, s2 = 0.0f;
    const size_t stride = (size_t)gridDim.x * blockDim.x;
    for (size_t idx = (size_t)blockIdx.x * blockDim.x + threadIdx.x; idx < n; idx += stride) {
        const float vv = x[idx];
        s += vv;
        s2 += vv * vv;
    }
#pragma unroll
    for (int o = 16; o > 0; o >>= 1) {
        s += __shfl_down_sync(0xFFFFFFFFu, s, o);
        s2 += __shfl_down_sync(0xFFFFFFFFu, s2, o);
    }
    __shared__ double sh[2][8];
    const int w = threadIdx.x >> 5, l = threadIdx.x & 31;
    if (l == 0) { sh[0][w] = (double)s; sh[1][w] = (double)s2; }
    __syncthreads();
    if (threadIdx.x == 0) {
        double a = 0.0, b = 0.0;
#pragma unroll
        for (int i = 0; i < 8; i++) { a += sh[0][i]; b += sh[1][i]; }
        g_part[blockIdx.x][0] = a;
        g_part[blockIdx.x][1] = b;
    }
}

__global__ void __launch_bounds__(256) red2_kernel(int nb)
{
    double a = 0.0, b = 0.0;
    for (int i = threadIdx.x; i < nb; i += 256) { a += g_part[i][0]; b += g_part[i][1]; }
    __shared__ double sa[256], sb[256];
    sa[threadIdx.x] = a;
    sb[threadIdx.x] = b;
    __syncthreads();
    for (int o = 128; o > 0; o >>= 1) {
        if (threadIdx.x < o) { sa[threadIdx.x] += sa[threadIdx.x + o]; sb[threadIdx.x] += sb[threadIdx.x + o]; }
        __syncthreads();
    }
    if (threadIdx.x == 0) { g_red[0] = sa[0]; g_red[1] = sb[0]; }
}

template <int OUTK> // 0 = fp32 only, 2 = also fp16
__global__ void __launch_bounds__(256) norm_kernel(
    const float* __restrict__ x, const float* __restrict__ alpha,
    const float* __restrict__ beta, const float* __restrict__ eps,
    float* __restrict__ y, __half* __restrict__ yh, size_t n)
{
    const double Md = (double)n;
    const double mean = g_red[0] / Md;
    const double var = (g_red[1] - Md * mean * mean) / (Md - 1.0);
    const float sd = (float)sqrt(var);

    const size_t n4 = n >> 2;
    const size_t stride = (size_t)gridDim.x * blockDim.x;
    for (size_t i4 = (size_t)blockIdx.x * blockDim.x + threadIdx.x; i4 < n4; i4 += stride) {
        float4 v = ((const float4*)x)[i4];
        const int d = (int)((i4 * 4) & (DD - 1));
        v.x = v.x / (sd + eps[d + 0]) * alpha[d + 0] + beta[d + 0];
        v.y = v.y / (sd + eps[d + 1]) * alpha[d + 1] + beta[d + 1];
        v.z = v.z / (sd + eps[d + 2]) * alpha[d + 2] + beta[d + 2];
        v.w = v.w / (sd + eps[d + 3]) * alpha[d + 3] + beta[d + 3];
        ((float4*)y)[i4] = v;
        if (OUTK == 2) {
            ((__half2*)yh)[i4 * 2 + 0] = __floats2half2_rn(v.x, v.y);
            ((__half2*)yh)[i4 * 2 + 1] = __floats2half2_rn(v.z, v.w);
        }
    }
}

// ===================== launch =====================
extern "C" void kernel_launch(void* const* d_in, const int* in_sizes, int n_in,
                              void* d_out, int out_size)
{
    const float* x    = (const float*)d_in[0];
    const float* wq_w = (const float*)d_in[1];
    const float* wq_b = (const float*)d_in[2];
    const float* wk_w = (const float*)d_in[3];
    const float* wk_b = (const float*)d_in[4];
    const float* wv_w = (const float*)d_in[5];
    const float* wv_b = (const float*)d_in[6];
    const float* wo_w = (const float*)d_in[7];
    const float* wo_b = (const float*)d_in[8];
    const float* w1   = (const float*)d_in[9];
    const float* b1   = (const float*)d_in[10];
    const float* w2   = (const float*)d_in[11];
    const float* b2   = (const float*)d_in[12];
    const float* an_a = (const float*)d_in[13];
    const float* an_b = (const float*)d_in[14];
    const float* an_e = (const float*)d_in[15];
    const float* mn_a = (const float*)d_in[16];
    const float* mn_b = (const float*)d_in[17];
    const float* mn_e = (const float*)d_in[18];
    float* out = (float*)d_out;

    float *attn, *out1, *G, *Wt, *WqC, *s, *rq, *rk, *cvec, *zero;
    cudaGetSymbolAddress((void**)&attn, g_attn);
    cudaGetSymbolAddress((void**)&out1, g_out1);
    cudaGetSymbolAddress((void**)&G, g_G);
    cudaGetSymbolAddress((void**)&Wt, g_Wt);
    cudaGetSymbolAddress((void**)&WqC, g_WqC);
    cudaGetSymbolAddress((void**)&s, g_s);
    cudaGetSymbolAddress((void**)&rq, g_rq);
    cudaGetSymbolAddress((void**)&rk, g_rk);
    cudaGetSymbolAddress((void**)&cvec, g_cvec);
    cudaGetSymbolAddress((void**)&zero, g_zero);

    __nv_bfloat16 *xhi, *xlo, *xThi, *xTlo, *Chi, *Clo, *WoMhi, *WoMlo, *Ehi, *Elo;
    __nv_bfloat16 *wqh, *wql, *wvTh, *wvTl;
    cudaGetSymbolAddress((void**)&xhi, g_xhi);     cudaGetSymbolAddress((void**)&xlo, g_xlo);
    cudaGetSymbolAddress((void**)&xThi, g_xThi);   cudaGetSymbolAddress((void**)&xTlo, g_xTlo);
    cudaGetSymbolAddress((void**)&Chi, g_Chi);     cudaGetSymbolAddress((void**)&Clo, g_Clo);
    cudaGetSymbolAddress((void**)&WoMhi, g_WoMhi); cudaGetSymbolAddress((void**)&WoMlo, g_WoMlo);
    cudaGetSymbolAddress((void**)&Ehi, g_Ehi);     cudaGetSymbolAddress((void**)&Elo, g_Elo);
    cudaGetSymbolAddress((void**)&wqh, g_wqhi);    cudaGetSymbolAddress((void**)&wql, g_wqlo);
    cudaGetSymbolAddress((void**)&wvTh, g_wvThi);  cudaGetSymbolAddress((void**)&wvTl, g_wvTlo);

    __half *w1f, *w2f, *atf, *hf;
    cudaGetSymbolAddress((void**)&w1f, g_w1f);
    cudaGetSymbolAddress((void**)&w2f, g_w2f);
    cudaGetSymbolAddress((void**)&atf, g_atf);
    cudaGetSymbolAddress((void**)&hf, g_hf);

    cudaFuncSetAttribute(gemm_mma<false, 1, true >, cudaFuncAttributeMaxDynamicSharedMemorySize, GW_SMEM);
    cudaFuncSetAttribute(gemm_mma<false, 0, false>, cudaFuncAttributeMaxDynamicSharedMemorySize, GW_SMEM);
    cudaFuncSetAttribute(gemm_mma<false, 1, false>, cudaFuncAttributeMaxDynamicSharedMemorySize, GW_SMEM);
    cudaFuncSetAttribute(gemm_mma<true,  0, false>, cudaFuncAttributeMaxDynamicSharedMemorySize, GW_SMEM);
    cudaFuncSetAttribute(gemm_f16<false, true,  true >, cudaFuncAttributeMaxDynamicSharedMemorySize, F16_SMEM);
    cudaFuncSetAttribute(gemm_f16<true,  false, false>, cudaFuncAttributeMaxDynamicSharedMemorySize, F16_SMEM);

    // ---- conversions ----
    split_kernel<<<1024, 256>>>(x, xhi, xlo, TOT / 4);
    splitT_kernel<<<dim3(DD / 32, MM / 32), 256>>>(x, xThi, xTlo, MM, DD);
    split_kernel<<<512, 256>>>(wq_w, wqh, wql, (size_t)DD * DD / 4);
    splitT_kernel<<<dim3(DD / 32, DD / 32), 256>>>(wv_w, wvTh, wvTl, DD, DD);
    cvtf16_kernel<<<1024, 256>>>(w1, w1f, (size_t)FF * DD / 4);
    cvtf16_kernel<<<1024, 256>>>(w2, w2f, (size_t)DD * FF / 4);

    // ---- bias-correction vectors (exact; zero when biases are zero) ----
    sums_kernel<<<dim3(BB, DD / 256), 256>>>(x, s);
    rqrk_kernel<<<dim3(BB, DD / 128), 128>>>(wq_w, wk_w, s, rq, rk);

    // ---- C_b = X_b^T X_b (symmetric; upper blocks + mirror) ----
    gemm_mma<false, 1, true><<<dim3(8, 8, BB), 256, GW_SMEM>>>(
        xThi, xTlo, xThi, xTlo, zero, nullptr, nullptr, Chi, Clo,
        NN, MM, MM, DD, (long long)NN, (long long)NN, (long long)DD * DD, 0);
    mirror_kernel<<<dim3(1024, BB), 256>>>(Chi, Clo);

    // ---- WqC_b = Wq * C_b ----
    gemm_mma<false, 0, false><<<dim3(8, 8, BB), 256, GW_SMEM>>>(
        wqh, wql, Chi, Clo, zero, nullptr, WqC, nullptr, nullptr,
        DD, DD, DD, DD, 0, (long long)DD * DD, (long long)DD * DD, 0);

    // ---- G, weights ----
    G_kernel<<<BB * HH, 256>>>(WqC, wk_w, wq_b, wk_b, rq, rk, G);
    weights_kernel<<<BB * HH, 256>>>(G, Wt);

    // ---- E_b = (Wo M_b) Wv ; c_b = Wo M_b bv + bo ----
    wom_kernel<<<dim3(DD / DH, HH, BB), 256>>>(wo_w, Wt, WoMhi, WoMlo);
    mvc_kernel<<<BB, 256>>>(Wt, wv_b, wo_w, wo_b, cvec);
    gemm_mma<false, 1, false><<<dim3(8, 8, BB), 256, GW_SMEM>>>(
        WoMhi, WoMlo, wvTh, wvTl, zero, nullptr, nullptr, Ehi, Elo,
        DD, DD, DD, DD, (long long)DD * DD, 0, (long long)DD * DD, 0);

    // ---- attn = X E_b^T + c_b + x ----
    gemm_mma<true, 0, false><<<dim3(8, NN / 128, BB), 256, GW_SMEM>>>(
        xhi, xlo, Ehi, Elo, cvec, x, attn, nullptr, nullptr,
        DD, DD, DD, DD, (long long)NN * DD, (long long)DD * DD, (long long)NN * DD, DD);

    // ---- rmsnorm 1 (global std), also emits fp16 for MLP1 ----
    red1_kernel<<<2048, 256>>>(attn, TOT);
    red2_kernel<<<1, 256>>>(2048);
    norm_kernel<2><<<2048, 256>>>(attn, an_a, an_b, an_e, attn, atf, TOT);

    // ---- MLP (fp16 single-product) ----
    gemm_f16<false, true, true><<<dim3(FF / 128, MM / 128), 256, F16_SMEM>>>(
        atf, w1f, b1, nullptr, nullptr, hf, MM, FF, DD);
    gemm_f16<true, false, false><<<dim3(DD / 128, MM / 128), 256, F16_SMEM>>>(
        hf, w2f, b2, attn, out1, nullptr, MM, DD, FF);

    // ---- rmsnorm 2 -> final output ----
    red1_kernel<<<2048, 256>>>(out1, TOT);
    red2_kernel<<<1, 256>>>(2048);
    norm_kernel<0><<<2048, 256>>>(out1, mn_a, mn_b, mn_e, out, nullptr, TOT);
}

// round 8
// speedup vs baseline: 1.0688x; 1.0688x over previous
#include <cuda_runtime.h>
#include <cuda_bf16.h>
#include <cuda_fp16.h>
#include <cstdint>
#include <math.h>

// Problem dims (fixed by the dataset)
#define BB 4
#define NN 4096
#define DD 1024
#define HH 16
#define DH 64
#define FF 4096
#define MM (BB * NN)          // 16384
#define TOT ((size_t)MM * DD) // 16,777,216

// ===================== helpers =====================
__device__ __forceinline__ uint32_t smem_u32(const void* p) {
    uint32_t a;
    asm("{ .reg .u64 t; cvta.to.shared.u64 t, %1; cvt.u32.u64 %0, t; }" : "=r"(a) : "l"(p));
    return a;
}
__device__ __forceinline__ void cp_async16(uint32_t dst, const void* src) {
    asm volatile("cp.async.cg.shared.global [%0], [%1], 16;"
                 :: "r"(dst), "l"(__cvta_generic_to_global(src)));
}
__device__ __forceinline__ void cp_commit() { asm volatile("cp.async.commit_group;" ::: "memory"); }
__device__ __forceinline__ void cp_wait0()  { asm volatile("cp.async.wait_group 0;" ::: "memory"); }
__device__ __forceinline__ void cp_wait1()  { asm volatile("cp.async.wait_group 1;" ::: "memory"); }

#define MMA16816(d, a, b0, b1) \
    asm volatile("mma.sync.aligned.m16n8k16.row.col.f32.bf16.bf16.f32 " \
        "{%0,%1,%2,%3}, {%4,%5,%6,%7}, {%8,%9}, {%0,%1,%2,%3};" \
        : "+f"((d)[0]), "+f"((d)[1]), "+f"((d)[2]), "+f"((d)[3]) \
        : "r"((a)[0]), "r"((a)[1]), "r"((a)[2]), "r"((a)[3]), "r"(b0), "r"(b1))

#define MMAF16(d, a, b0, b1) \
    asm volatile("mma.sync.aligned.m16n8k16.row.col.f32.f16.f16.f32 " \
        "{%0,%1,%2,%3}, {%4,%5,%6,%7}, {%8,%9}, {%0,%1,%2,%3};" \
        : "+f"((d)[0]), "+f"((d)[1]), "+f"((d)[2]), "+f"((d)[3]) \
        : "r"((a)[0]), "r"((a)[1]), "r"((a)[2]), "r"((a)[3]), "r"(b0), "r"(b1))

#define LDMX4(r, addr) \
    asm volatile("ldmatrix.sync.aligned.m8n8.x4.shared.b16 {%0,%1,%2,%3}, [%4];" \
        : "=r"((r)[0]), "=r"((r)[1]), "=r"((r)[2]), "=r"((r)[3]) : "r"(addr))

// ===================== scratch (static device globals) =====================
__device__ float g_q[MM * DD];
__device__ float g_k[MM * DD];
__device__ float g_attn[MM * DD];
__device__ float g_out1[MM * DD];
__device__ float g_Gpart[BB * HH * 8 * DH * DH];
__device__ float g_Wt[BB * HH * DH * DH];
__device__ float g_cvec[BB * DD];
__device__ float g_zero[DD];          // never written: stays 0
__device__ double g_part[4096][2];
__device__ double g_red[2];

__device__ __nv_bfloat16 g_xhi[MM * DD],  g_xlo[MM * DD];
__device__ __nv_bfloat16 g_WoMhi[BB * DD * DD], g_WoMlo[BB * DD * DD];
__device__ __nv_bfloat16 g_Ehi[BB * DD * DD],  g_Elo[BB * DD * DD];
__device__ __nv_bfloat16 g_wqhi[DD * DD], g_wqlo[DD * DD];
__device__ __nv_bfloat16 g_wkhi[DD * DD], g_wklo[DD * DD];
__device__ __nv_bfloat16 g_wvThi[DD * DD], g_wvTlo[DD * DD];

// fp16 MLP path
__device__ __half g_w1f[FF * DD];
__device__ __half g_w2f[DD * FF];
__device__ __half g_atf[MM * DD];
__device__ __half g_hf[(size_t)MM * FF];

// ===================== fp32 -> bf16 hi/lo split =====================
__global__ void __launch_bounds__(256) split_kernel(
    const float* __restrict__ src, __nv_bfloat16* __restrict__ hi,
    __nv_bfloat16* __restrict__ lo, size_t n4)
{
    const size_t stride = (size_t)gridDim.x * blockDim.x;
    for (size_t i4 = (size_t)blockIdx.x * blockDim.x + threadIdx.x; i4 < n4; i4 += stride) {
        float4 v = ((const float4*)src)[i4];
        __nv_bfloat16 h0 = __float2bfloat16(v.x);
        __nv_bfloat16 h1 = __float2bfloat16(v.y);
        __nv_bfloat16 h2 = __float2bfloat16(v.z);
        __nv_bfloat16 h3 = __float2bfloat16(v.w);
        __nv_bfloat162 hA; hA.x = h0; hA.y = h1;
        __nv_bfloat162 hB; hB.x = h2; hB.y = h3;
        __nv_bfloat162 lA; lA.x = __float2bfloat16(v.x - __bfloat162float(h0));
                           lA.y = __float2bfloat16(v.y - __bfloat162float(h1));
        __nv_bfloat162 lB; lB.x = __float2bfloat16(v.z - __bfloat162float(h2));
                           lB.y = __float2bfloat16(v.w - __bfloat162float(h3));
        ((__nv_bfloat162*)hi)[i4 * 2 + 0] = hA;
        ((__nv_bfloat162*)hi)[i4 * 2 + 1] = hB;
        ((__nv_bfloat162*)lo)[i4 * 2 + 0] = lA;
        ((__nv_bfloat162*)lo)[i4 * 2 + 1] = lB;
    }
}

// transposed split: src [R][C] fp32 -> hi/lo [C][R] bf16
__global__ void __launch_bounds__(256) splitT_kernel(
    const float* __restrict__ src, __nv_bfloat16* __restrict__ hi,
    __nv_bfloat16* __restrict__ lo, int R, int C)
{
    __shared__ float t[32][33];
    const int c0 = blockIdx.x * 32, r0 = blockIdx.y * 32;
    const int tx = threadIdx.x & 31, ty = threadIdx.x >> 5; // 32 x 8
    for (int rr = ty; rr < 32; rr += 8)
        t[rr][tx] = src[(size_t)(r0 + rr) * C + c0 + tx];
    __syncthreads();
    for (int cc = ty; cc < 32; cc += 8) {
        const float v = t[tx][cc];
        const __nv_bfloat16 h = __float2bfloat16(v);
        const size_t o = (size_t)(c0 + cc) * R + r0 + tx;
        hi[o] = h;
        lo[o] = __float2bfloat16(v - __bfloat162float(h));
    }
}

// ===================== fp32 -> fp16 convert =====================
__global__ void __launch_bounds__(256) cvtf16_kernel(
    const float* __restrict__ src, __half* __restrict__ dst, size_t n4)
{
    const size_t stride = (size_t)gridDim.x * blockDim.x;
    for (size_t i4 = (size_t)blockIdx.x * blockDim.x + threadIdx.x; i4 < n4; i4 += stride) {
        float4 v = ((const float4*)src)[i4];
        ((__half2*)dst)[i4 * 2 + 0] = __floats2half2_rn(v.x, v.y);
        ((__half2*)dst)[i4 * 2 + 1] = __floats2half2_rn(v.z, v.w);
    }
}

// ===================== bf16 hi/lo HMMA GEMM (3 products), batched/strided =====================
#define GW_BM 128
#define GW_BN 128
#define GW_BK 32
#define ROWB 80
#define BUFB (128 * ROWB)
#define STAGEB (4 * BUFB)
#define GW_SMEM (2 * STAGEB)       // 81920

// C[z][m,n] = sum_k A[z][m,k] * W[z][n,k] + bias[z][n] (+res)
template <bool HAS_RES, int OUTMODE> // OUTMODE 0: fp32; 1: bf16 hi/lo
__global__ void __launch_bounds__(256, 2) gemm_mma(
    const __nv_bfloat16* __restrict__ Ahi, const __nv_bfloat16* __restrict__ Alo,
    const __nv_bfloat16* __restrict__ Whi, const __nv_bfloat16* __restrict__ Wlo,
    const float* __restrict__ bias, const float* __restrict__ res,
    float* __restrict__ Cf, __nv_bfloat16* __restrict__ Chi, __nv_bfloat16* __restrict__ Clo,
    int K, int lda, int ldw, int ldc,
    long long saA, long long saW, long long saC, int saBias)
{
    extern __shared__ char sm[];
    const int z = blockIdx.z;
    Ahi += (size_t)z * saA;  Alo += (size_t)z * saA;
    Whi += (size_t)z * saW;  Wlo += (size_t)z * saW;
    bias += (size_t)z * saBias;
    if (HAS_RES) res += (size_t)z * saC;
    if (OUTMODE == 0) Cf += (size_t)z * saC;
    else { Chi += (size_t)z * saC; Clo += (size_t)z * saC; }

    const int tid = threadIdx.x;
    const int wid = tid >> 5;
    const int lane = tid & 31;
    const int wm = wid & 3;
    const int wn = wid >> 2;
    const int bm = blockIdx.y * GW_BM;
    const int bn = blockIdx.x * GW_BN;
    const int KT = K / GW_BK;
    const uint32_t smb = smem_u32(sm);

    auto load_stage = [&](int kt, uint32_t sb) {
        const int k0 = kt * GW_BK;
#pragma unroll
        for (int i = 0; i < 8; i++) {
            const int c = tid + i * 256;
            const int buf = c >> 9;           // 0:Ahi 1:Alo 2:Whi 3:Wlo
            const int cc = c & 511;
            const int row = cc >> 2;
            const int qq = cc & 3;
            const __nv_bfloat16* gb = (buf == 0) ? Ahi : (buf == 1) ? Alo
                                     : (buf == 2) ? Whi : Wlo;
            const int ld = (buf < 2) ? lda : ldw;
            const int grow = ((buf < 2) ? bm : bn) + row;
            const void* src = gb + (size_t)grow * ld + k0 + qq * 8;
            cp_async16(sb + buf * BUFB + row * ROWB + qq * 16, src);
        }
    };

    float acc[2][8][4];
#pragma unroll
    for (int mt = 0; mt < 2; mt++)
#pragma unroll
        for (int nt = 0; nt < 8; nt++)
#pragma unroll
            for (int r = 0; r < 4; r++) acc[mt][nt][r] = 0.0f;

    load_stage(0, smb);
    cp_commit();

    const int lr = lane & 7;
    const int a_row = wm * 32 + lr + ((lane & 8) ? 8 : 0);
    const int a_kb  = (lane & 16) ? 16 : 0;
    const int b_row = wn * 64 + lr + ((lane & 16) ? 8 : 0);
    const int b_kb  = (lane & 8) ? 16 : 0;

    for (int kt = 0; kt < KT; kt++) {
        const uint32_t sb = smb + (uint32_t)(kt & 1) * STAGEB;
        if (kt + 1 < KT) {
            load_stage(kt + 1, smb + (uint32_t)((kt + 1) & 1) * STAGEB);
            cp_commit();
            cp_wait1();
        } else {
            cp_wait0();
        }
        __syncthreads();

        const uint32_t As = sb;
        const uint32_t Bs = sb + 2 * BUFB;

#pragma unroll
        for (int k16 = 0; k16 < 2; k16++) {
            const int kc = k16 * 32;
            uint32_t ah[2][4], al[2][4];
#pragma unroll
            for (int mt = 0; mt < 2; mt++) {
                const uint32_t aAddr = As + (uint32_t)((a_row + mt * 16) * ROWB + kc + a_kb);
                LDMX4(ah[mt], aAddr);
                LDMX4(al[mt], aAddr + BUFB);
            }
#pragma unroll
            for (int p = 0; p < 4; p++) {
                uint32_t bh[4], bl[4];
                const uint32_t bAddr = Bs + (uint32_t)((b_row + p * 16) * ROWB + kc + b_kb);
                LDMX4(bh, bAddr);
                LDMX4(bl, bAddr + BUFB);
#pragma unroll
                for (int sub = 0; sub < 2; sub++) {
                    const int nt = p * 2 + sub;
                    const uint32_t b0h = bh[sub * 2], b1h = bh[sub * 2 + 1];
                    const uint32_t b0l = bl[sub * 2], b1l = bl[sub * 2 + 1];
#pragma unroll
                    for (int mt = 0; mt < 2; mt++) {
                        MMA16816(acc[mt][nt], ah[mt], b0h, b1h);
                        MMA16816(acc[mt][nt], ah[mt], b0l, b1l);
                        MMA16816(acc[mt][nt], al[mt], b0h, b1h);
                    }
                }
            }
        }
        __syncthreads();
    }

#pragma unroll
    for (int mt = 0; mt < 2; mt++) {
        const int r0 = bm + wm * 32 + mt * 16 + (lane >> 2);
#pragma unroll
        for (int nt = 0; nt < 8; nt++) {
            const int c = bn + wn * 64 + nt * 8 + ((lane & 3) << 1);
            const float b0 = bias[c], b1 = bias[c + 1];
#pragma unroll
            for (int half = 0; half < 2; half++) {
                const int row = r0 + half * 8;
                float v0 = acc[mt][nt][half * 2 + 0] + b0;
                float v1 = acc[mt][nt][half * 2 + 1] + b1;
                if (HAS_RES) {
                    const float2 rr = *(const float2*)(res + (size_t)row * ldc + c);
                    v0 += rr.x; v1 += rr.y;
                }
                if (OUTMODE == 0) {
                    float2 o; o.x = v0; o.y = v1;
                    *(float2*)(Cf + (size_t)row * ldc + c) = o;
                } else {
                    __nv_bfloat162 h, l;
                    h.x = __float2bfloat16(v0);
                    h.y = __float2bfloat16(v1);
                    l.x = __float2bfloat16(v0 - __bfloat162float(h.x));
                    l.y = __float2bfloat16(v1 - __bfloat162float(h.y));
                    *(__nv_bfloat162*)(Chi + (size_t)row * ldc + c) = h;
                    *(__nv_bfloat162*)(Clo + (size_t)row * ldc + c) = l;
                }
            }
        }
    }
}

// ===================== fp16 single-product HMMA GEMM (MLP path) =====================
#define F16_STAGEB (2 * BUFB)
#define F16_SMEM (2 * F16_STAGEB)

template <bool HAS_RES, bool GELU, bool OUTF16>
__global__ void __launch_bounds__(256, 2) gemm_f16(
    const __half* __restrict__ A, const __half* __restrict__ B,
    const float* __restrict__ bias, const float* __restrict__ res,
    float* __restrict__ Cf, __half* __restrict__ Ch,
    int M, int N, int K)
{
    extern __shared__ char sm[];
    const int tid = threadIdx.x;
    const int wid = tid >> 5;
    const int lane = tid & 31;
    const int wm = wid & 3;
    const int wn = wid >> 2;
    const int bm = blockIdx.y * GW_BM;
    const int bn = blockIdx.x * GW_BN;
    const int KT = K / GW_BK;
    const uint32_t smb = smem_u32(sm);

    auto load_stage = [&](int kt, uint32_t sb) {
        const int k0 = kt * GW_BK;
#pragma unroll
        for (int i = 0; i < 4; i++) {
            const int c = tid + i * 256;
            const int buf = c >> 9;
            const int cc = c & 511;
            const int row = cc >> 2;
            const int qq = cc & 3;
            const __half* gb = buf ? B : A;
            const int grow = (buf ? bn : bm) + row;
            const void* src = gb + (size_t)grow * K + k0 + qq * 8;
            cp_async16(sb + buf * BUFB + row * ROWB + qq * 16, src);
        }
    };

    float acc[2][8][4];
#pragma unroll
    for (int mt = 0; mt < 2; mt++)
#pragma unroll
        for (int nt = 0; nt < 8; nt++)
#pragma unroll
            for (int r = 0; r < 4; r++) acc[mt][nt][r] = 0.0f;

    load_stage(0, smb);
    cp_commit();

    const int lr = lane & 7;
    const int a_row = wm * 32 + lr + ((lane & 8) ? 8 : 0);
    const int a_kb  = (lane & 16) ? 16 : 0;
    const int b_row = wn * 64 + lr + ((lane & 16) ? 8 : 0);
    const int b_kb  = (lane & 8) ? 16 : 0;

    for (int kt = 0; kt < KT; kt++) {
        const uint32_t sb = smb + (uint32_t)(kt & 1) * F16_STAGEB;
        if (kt + 1 < KT) {
            load_stage(kt + 1, smb + (uint32_t)((kt + 1) & 1) * F16_STAGEB);
            cp_commit();
            cp_wait1();
        } else {
            cp_wait0();
        }
        __syncthreads();

        const uint32_t As = sb;
        const uint32_t Bs = sb + BUFB;

#pragma unroll
        for (int k16 = 0; k16 < 2; k16++) {
            const int kc = k16 * 32;
            uint32_t af[2][4];
#pragma unroll
            for (int mt = 0; mt < 2; mt++)
                LDMX4(af[mt], As + (uint32_t)((a_row + mt * 16) * ROWB + kc + a_kb));
#pragma unroll
            for (int p = 0; p < 4; p++) {
                uint32_t bf[4];
                LDMX4(bf, Bs + (uint32_t)((b_row + p * 16) * ROWB + kc + b_kb));
#pragma unroll
                for (int sub = 0; sub < 2; sub++) {
                    const int nt = p * 2 + sub;
#pragma unroll
                    for (int mt = 0; mt < 2; mt++)
                        MMAF16(acc[mt][nt], af[mt], bf[sub * 2], bf[sub * 2 + 1]);
                }
            }
        }
        __syncthreads();
    }

#pragma unroll
    for (int mt = 0; mt < 2; mt++) {
        const int r0 = bm + wm * 32 + mt * 16 + (lane >> 2);
#pragma unroll
        for (int nt = 0; nt < 8; nt++) {
            const int c = bn + wn * 64 + nt * 8 + ((lane & 3) << 1);
            const float b0 = bias[c], b1 = bias[c + 1];
#pragma unroll
            for (int half = 0; half < 2; half++) {
                const int row = r0 + half * 8;
                float v0 = acc[mt][nt][half * 2 + 0] + b0;
                float v1 = acc[mt][nt][half * 2 + 1] + b1;
                if (HAS_RES) {
                    const float2 rr = *(const float2*)(res + (size_t)row * N + c);
                    v0 += rr.x; v1 += rr.y;
                }
                if (GELU) {
                    v0 = 0.5f * v0 * (1.0f + erff(v0 * 0.70710678118654752f));
                    v1 = 0.5f * v1 * (1.0f + erff(v1 * 0.70710678118654752f));
                }
                if (OUTF16) {
                    *(__half2*)(Ch + (size_t)row * N + c) = __floats2half2_rn(v0, v1);
                } else {
                    float2 o; o.x = v0; o.y = v1;
                    *(float2*)(Cf + (size_t)row * N + c) = o;
                }
            }
        }
    }
}

// ===================== attention small ops (R5-verified) =====================
__global__ void __launch_bounds__(256) gram_kernel(
    const float* __restrict__ q, const float* __restrict__ k,
    float* __restrict__ Gpart)
{
    const int bh = blockIdx.x;
    const int ns = blockIdx.y;
    const int b = bh >> 4, h = bh & 15;
    const int tid = threadIdx.x;
    __shared__ float Qs[32][68];
    __shared__ float Ks[32][68];

    float acc[4][4];
#pragma unroll
    for (int i = 0; i < 4; i++)
#pragma unroll
        for (int j = 0; j < 4; j++) acc[i][j] = 0.0f;

    const int ty = tid >> 4, tx = tid & 15;
    const size_t base = ((size_t)b * NN) * DD + h * DH;
    const int n0s = ns * 512;

    for (int n0 = n0s; n0 < n0s + 512; n0 += 32) {
#pragma unroll
        for (int r = 0; r < 2; r++) {
            int idx4 = tid + r * 256;
            int nn = idx4 >> 4;
            int i4 = (idx4 & 15) * 4;
            float4 qv = *(const float4*)(q + base + (size_t)(n0 + nn) * DD + i4);
            float4 kv = *(const float4*)(k + base + (size_t)(n0 + nn) * DD + i4);
            *(float4*)&Qs[nn][i4] = qv;
            *(float4*)&Ks[nn][i4] = kv;
        }
        __syncthreads();
#pragma unroll
        for (int kk = 0; kk < 32; kk++) {
            float qr[4], kr[4];
#pragma unroll
            for (int i = 0; i < 4; i++) qr[i] = Qs[kk][ty * 4 + i];
#pragma unroll
            for (int j = 0; j < 4; j++) kr[j] = Ks[kk][tx * 4 + j];
#pragma unroll
            for (int i = 0; i < 4; i++)
#pragma unroll
                for (int j = 0; j < 4; j++) acc[i][j] += qr[i] * kr[j];
        }
        __syncthreads();
    }

    float* Gout = Gpart + ((size_t)bh * 8 + ns) * (DH * DH);
#pragma unroll
    for (int i = 0; i < 4; i++)
#pragma unroll
        for (int j = 0; j < 4; j++)
            Gout[(ty * 4 + i) * DH + tx * 4 + j] = acc[i][j];
}

__global__ void __launch_bounds__(256) weights_kernel(
    const float* __restrict__ Gpart, float* __restrict__ Wt)
{
    const int bh = blockIdx.x;
    const int tid = threadIdx.x;
    __shared__ float Gs[DH][DH];
    __shared__ float ct[DH], st[DH];

    for (int e = tid; e < DH * DH; e += 256) {
        float sacc = 0.0f;
#pragma unroll
        for (int p = 0; p < 8; p++)
            sacc += Gpart[((size_t)bh * 8 + p) * (DH * DH) + e];
        Gs[e >> 6][e & 63] = sacc;
    }
    if (tid < DH) {
        float a = 6.283185307179586f * (float)tid / 64.0f;
        ct[tid] = cosf(a);
        st[tid] = sinf(a);
    }
    __syncthreads();

    const int i = tid >> 2;
    const int j0 = (tid & 3) * 16;
    for (int jj = 0; jj < 16; jj++) {
        const int j = j0 + jj;
        float re = 0.0f, im = 0.0f;
#pragma unroll
        for (int kk = 0; kk < DH; kk++) {
            const int t = (kk * j) & 63;
            const float g = Gs[i][kk];
            re += g * ct[t];
            im += g * st[t];
        }
        Wt[(size_t)bh * (DH * DH) + i * DH + j] = sqrtf(re * re + im * im);
    }
}

// (Wo M_b)[o, h*64+j] = sum_i Wo[o, h*64+i] * Wt[b*16+h][i][j]  -> bf16 hi/lo  (R7-verified)
__global__ void __launch_bounds__(256) wom_kernel(
    const float* __restrict__ wo, const float* __restrict__ Wt,
    __nv_bfloat16* __restrict__ WoMhi, __nv_bfloat16* __restrict__ WoMlo)
{
    const int ot = blockIdx.x, h = blockIdx.y, b = blockIdx.z;
    const int tid = threadIdx.x;
    __shared__ float Os[DH][DH + 1];
    __shared__ float Ms[DH][DH + 1];

    const int lrow = tid >> 2;
    const int lcol = (tid & 3) * 16;
#pragma unroll
    for (int q = 0; q < 4; q++) {
        float4 ov = *(const float4*)(wo + (size_t)(ot * DH + lrow) * DD + h * DH + lcol + q * 4);
        float4 mv4 = *(const float4*)(Wt + (size_t)(b * HH + h) * (DH * DH) + lrow * DH + lcol + q * 4);
        Os[lrow][lcol + q * 4 + 0] = ov.x;  Os[lrow][lcol + q * 4 + 1] = ov.y;
        Os[lrow][lcol + q * 4 + 2] = ov.z;  Os[lrow][lcol + q * 4 + 3] = ov.w;
        Ms[lrow][lcol + q * 4 + 0] = mv4.x; Ms[lrow][lcol + q * 4 + 1] = mv4.y;
        Ms[lrow][lcol + q * 4 + 2] = mv4.z; Ms[lrow][lcol + q * 4 + 3] = mv4.w;
    }
    __syncthreads();

    const int ty = tid >> 4, tx = tid & 15;
#pragma unroll
    for (int oo = 0; oo < 4; oo++) {
        const int o = ty * 4 + oo;
        float vr[4] = {0.f, 0.f, 0.f, 0.f};
        for (int i = 0; i < DH; i++) {
            const float a = Os[o][i];
#pragma unroll
            for (int jj = 0; jj < 4; jj++) vr[jj] += a * Ms[i][tx * 4 + jj];
        }
#pragma unroll
        for (int jj = 0; jj < 4; jj++) {
            const size_t idx = (size_t)b * DD * DD + (size_t)(ot * DH + o) * DD + h * DH + tx * 4 + jj;
            const __nv_bfloat16 hv = __float2bfloat16(vr[jj]);
            WoMhi[idx] = hv;
            WoMlo[idx] = __float2bfloat16(vr[jj] - __bfloat162float(hv));
        }
    }
}

// c_b = Wo (M_b bv) + bo  (R7-verified)
__global__ void __launch_bounds__(256) mvc_kernel(
    const float* __restrict__ Wt, const float* __restrict__ bv,
    const float* __restrict__ wo, const float* __restrict__ bo,
    float* __restrict__ cvec)
{
    const int b = blockIdx.x;
    const int tid = threadIdx.x;
    __shared__ float mv[DD];
    for (int f = tid; f < DD; f += 256) {
        const int h = f >> 6, i = f & 63;
        float sacc = 0.0f;
        const float* wrow = Wt + (size_t)(b * HH + h) * (DH * DH) + i * DH;
        for (int j = 0; j < DH; j++) sacc += wrow[j] * bv[h * DH + j];
        mv[f] = sacc;
    }
    __syncthreads();
    for (int o = tid; o < DD; o += 256) {
        float sacc = 0.0f;
        const float* wrow = wo + (size_t)o * DD;
        for (int f = 0; f < DD; f++) sacc += wrow[f] * mv[f];
        cvec[b * DD + o] = sacc + bo[o];
    }
}

// ===================== global-std reduction + norm =====================
__global__ void __launch_bounds__(256) red1_kernel(const float* __restrict__ x, size_t n)
{
    float s = 0.0f, s2 = 0.0f;
    const size_t stride = (size_t)gridDim.x * blockDim.x;
    for (size_t idx = (size_t)blockIdx.x * blockDim.x + threadIdx.x; idx < n; idx += stride) {
        const float vv = x[idx];
        s += vv;
        s2 += vv * vv;
    }
#pragma unroll
    for (int o = 16; o > 0; o >>= 1) {
        s += __shfl_down_sync(0xFFFFFFFFu, s, o);
        s2 += __shfl_down_sync(0xFFFFFFFFu, s2, o);
    }
    __shared__ double sh[2][8];
    const int w = threadIdx.x >> 5, l = threadIdx.x & 31;
    if (l == 0) { sh[0][w] = (double)s; sh[1][w] = (double)s2; }
    __syncthreads();
    if (threadIdx.x == 0) {
        double a = 0.0, b = 0.0;
#pragma unroll
        for (int i = 0; i < 8; i++) { a += sh[0][i]; b += sh[1][i]; }
        g_part[blockIdx.x][0] = a;
        g_part[blockIdx.x][1] = b;
    }
}

__global__ void __launch_bounds__(256) red2_kernel(int nb)
{
    double a = 0.0, b = 0.0;
    for (int i = threadIdx.x; i < nb; i += 256) { a += g_part[i][0]; b += g_part[i][1]; }
    __shared__ double sa[256], sb[256];
    sa[threadIdx.x] = a;
    sb[threadIdx.x] = b;
    __syncthreads();
    for (int o = 128; o > 0; o >>= 1) {
        if (threadIdx.x < o) { sa[threadIdx.x] += sa[threadIdx.x + o]; sb[threadIdx.x] += sb[threadIdx.x + o]; }
        __syncthreads();
    }
    if (threadIdx.x == 0) { g_red[0] = sa[0]; g_red[1] = sb[0]; }
}

template <int OUTK> // 0 = fp32 only, 2 = also fp16
__global__ void __launch_bounds__(256) norm_kernel(
    const float* __restrict__ x, const float* __restrict__ alpha,
    const float* __restrict__ beta, const float* __restrict__ eps,
    float* __restrict__ y, __half* __restrict__ yh, size_t n)
{
    const double Md = (double)n;
    const double mean = g_red[0] / Md;
    const double var = (g_red[1] - Md * mean * mean) / (Md - 1.0);
    const float sd = (float)sqrt(var);

    const size_t n4 = n >> 2;
    const size_t stride = (size_t)gridDim.x * blockDim.x;
    for (size_t i4 = (size_t)blockIdx.x * blockDim.x + threadIdx.x; i4 < n4; i4 += stride) {
        float4 v = ((const float4*)x)[i4];
        const int d = (int)((i4 * 4) & (DD - 1));
        v.x = v.x / (sd + eps[d + 0]) * alpha[d + 0] + beta[d + 0];
        v.y = v.y / (sd + eps[d + 1]) * alpha[d + 1] + beta[d + 1];
        v.z = v.z / (sd + eps[d + 2]) * alpha[d + 2] + beta[d + 2];
        v.w = v.w / (sd + eps[d + 3]) * alpha[d + 3] + beta[d + 3];
        ((float4*)y)[i4] = v;
        if (OUTK == 2) {
            ((__half2*)yh)[i4 * 2 + 0] = __floats2half2_rn(v.x, v.y);
            ((__half2*)yh)[i4 * 2 + 1] = __floats2half2_rn(v.z, v.w);
        }
    }
}

// ===================== launch =====================
extern "C" void kernel_launch(void* const* d_in, const int* in_sizes, int n_in,
                              void* d_out, int out_size)
{
    const float* x    = (const float*)d_in[0];
    const float* wq_w = (const float*)d_in[1];
    const float* wq_b = (const float*)d_in[2];
    const float* wk_w = (const float*)d_in[3];
    const float* wk_b = (const float*)d_in[4];
    const float* wv_w = (const float*)d_in[5];
    const float* wv_b = (const float*)d_in[6];
    const float* wo_w = (const float*)d_in[7];
    const float* wo_b = (const float*)d_in[8];
    const float* w1   = (const float*)d_in[9];
    const float* b1   = (const float*)d_in[10];
    const float* w2   = (const float*)d_in[11];
    const float* b2   = (const float*)d_in[12];
    const float* an_a = (const float*)d_in[13];
    const float* an_b = (const float*)d_in[14];
    const float* an_e = (const float*)d_in[15];
    const float* mn_a = (const float*)d_in[16];
    const float* mn_b = (const float*)d_in[17];
    const float* mn_e = (const float*)d_in[18];
    float* out = (float*)d_out;

    float *q, *k, *attn, *out1, *Gpart, *Wt, *cvec, *zero;
    cudaGetSymbolAddress((void**)&q, g_q);
    cudaGetSymbolAddress((void**)&k, g_k);
    cudaGetSymbolAddress((void**)&attn, g_attn);
    cudaGetSymbolAddress((void**)&out1, g_out1);
    cudaGetSymbolAddress((void**)&Gpart, g_Gpart);
    cudaGetSymbolAddress((void**)&Wt, g_Wt);
    cudaGetSymbolAddress((void**)&cvec, g_cvec);
    cudaGetSymbolAddress((void**)&zero, g_zero);

    __nv_bfloat16 *xhi, *xlo, *WoMhi, *WoMlo, *Ehi, *Elo;
    __nv_bfloat16 *wqh, *wql, *wkh, *wkl, *wvTh, *wvTl;
    cudaGetSymbolAddress((void**)&xhi, g_xhi);     cudaGetSymbolAddress((void**)&xlo, g_xlo);
    cudaGetSymbolAddress((void**)&WoMhi, g_WoMhi); cudaGetSymbolAddress((void**)&WoMlo, g_WoMlo);
    cudaGetSymbolAddress((void**)&Ehi, g_Ehi);     cudaGetSymbolAddress((void**)&Elo, g_Elo);
    cudaGetSymbolAddress((void**)&wqh, g_wqhi);    cudaGetSymbolAddress((void**)&wql, g_wqlo);
    cudaGetSymbolAddress((void**)&wkh, g_wkhi);    cudaGetSymbolAddress((void**)&wkl, g_wklo);
    cudaGetSymbolAddress((void**)&wvTh, g_wvThi);  cudaGetSymbolAddress((void**)&wvTl, g_wvTlo);

    __half *w1f, *w2f, *atf, *hf;
    cudaGetSymbolAddress((void**)&w1f, g_w1f);
    cudaGetSymbolAddress((void**)&w2f, g_w2f);
    cudaGetSymbolAddress((void**)&atf, g_atf);
    cudaGetSymbolAddress((void**)&hf, g_hf);

    cudaFuncSetAttribute(gemm_mma<false, 0>, cudaFuncAttributeMaxDynamicSharedMemorySize, GW_SMEM);
    cudaFuncSetAttribute(gemm_mma<false, 1>, cudaFuncAttributeMaxDynamicSharedMemorySize, GW_SMEM);
    cudaFuncSetAttribute(gemm_mma<true,  0>, cudaFuncAttributeMaxDynamicSharedMemorySize, GW_SMEM);
    cudaFuncSetAttribute(gemm_f16<false, true,  true >, cudaFuncAttributeMaxDynamicSharedMemorySize, F16_SMEM);
    cudaFuncSetAttribute(gemm_f16<true,  false, false>, cudaFuncAttributeMaxDynamicSharedMemorySize, F16_SMEM);

    // ---- conversions ----
    split_kernel<<<1024, 256>>>(x, xhi, xlo, TOT / 4);
    split_kernel<<<512, 256>>>(wq_w, wqh, wql, (size_t)DD * DD / 4);
    split_kernel<<<512, 256>>>(wk_w, wkh, wkl, (size_t)DD * DD / 4);
    splitT_kernel<<<dim3(DD / 32, DD / 32), 256>>>(wv_w, wvTh, wvTl, DD, DD);
    cvtf16_kernel<<<1024, 256>>>(w1, w1f, (size_t)FF * DD / 4);
    cvtf16_kernel<<<1024, 256>>>(w2, w2f, (size_t)DD * FF / 4);

    // ---- Q/K projections (bf16-3, biases exact) ----
    gemm_mma<false, 0><<<dim3(8, 128, 1), 256, GW_SMEM>>>(
        xhi, xlo, wqh, wql, wq_b, nullptr, q, nullptr, nullptr,
        DD, DD, DD, DD, 0, 0, 0, 0);
    gemm_mma<false, 0><<<dim3(8, 128, 1), 256, GW_SMEM>>>(
        xhi, xlo, wkh, wkl, wk_b, nullptr, k, nullptr, nullptr,
        DD, DD, DD, DD, 0, 0, 0, 0);

    // ---- Gram -> DFT magnitude weights ----
    gram_kernel<<<dim3(BB * HH, 8), 256>>>(q, k, Gpart);
    weights_kernel<<<BB * HH, 256>>>(Gpart, Wt);

    // ---- V/O collapse: E_b = (Wo M_b) Wv ; c_b = Wo M_b bv + bo ----
    wom_kernel<<<dim3(DD / DH, HH, BB), 256>>>(wo_w, Wt, WoMhi, WoMlo);
    mvc_kernel<<<BB, 256>>>(Wt, wv_b, wo_w, wo_b, cvec);
    gemm_mma<false, 1><<<dim3(8, 8, BB), 256, GW_SMEM>>>(
        WoMhi, WoMlo, wvTh, wvTl, zero, nullptr, nullptr, Ehi, Elo,
        DD, DD, DD, DD, (long long)DD * DD, 0, (long long)DD * DD, 0);

    // ---- attn = X E_b^T + c_b + x ----
    gemm_mma<true, 0><<<dim3(8, NN / 128, BB), 256, GW_SMEM>>>(
        xhi, xlo, Ehi, Elo, cvec, x, attn, nullptr, nullptr,
        DD, DD, DD, DD, (long long)NN * DD, (long long)DD * DD, (long long)NN * DD, DD);

    // ---- rmsnorm 1 (global std), also emits fp16 for MLP1 ----
    red1_kernel<<<2048, 256>>>(attn, TOT);
    red2_kernel<<<1, 256>>>(2048);
    norm_kernel<2><<<2048, 256>>>(attn, an_a, an_b, an_e, attn, atf, TOT);

    // ---- MLP (fp16 single-product) ----
    gemm_f16<false, true, true><<<dim3(FF / 128, MM / 128), 256, F16_SMEM>>>(
        atf, w1f, b1, nullptr, nullptr, hf, MM, FF, DD);
    gemm_f16<true, false, false><<<dim3(DD / 128, MM / 128), 256, F16_SMEM>>>(
        hf, w2f, b2, attn, out1, nullptr, MM, DD, FF);

    // ---- rmsnorm 2 -> final output ----
    red1_kernel<<<2048, 256>>>(out1, TOT);
    red2_kernel<<<1, 256>>>(2048);
    norm_kernel<0><<<2048, 256>>>(out1, mn_a, mn_b, mn_e, out, nullptr, TOT);
}

// round 10
// speedup vs baseline: 1.6243x; 1.5197x over previous
#include <cuda_runtime.h>
#include <cuda_fp16.h>
#include <cstdint>
#include <math.h>

// Problem dims (fixed by the dataset)
#define BB 4
#define NN 4096
#define DD 1024
#define HH 16
#define DH 64
#define FF 4096
#define MM (BB * NN)          // 16384
#define TOT ((size_t)MM * DD) // 16,777,216

// ===================== helpers =====================
__device__ __forceinline__ uint32_t smem_u32(const void* p) {
    uint32_t a;
    asm("{ .reg .u64 t; cvta.to.shared.u64 t, %1; cvt.u32.u64 %0, t; }" : "=r"(a) : "l"(p));
    return a;
}
__device__ __forceinline__ void cp_async16(uint32_t dst, const void* src) {
    asm volatile("cp.async.cg.shared.global [%0], [%1], 16;"
                 :: "r"(dst), "l"(__cvta_generic_to_global(src)));
}
__device__ __forceinline__ void cp_commit() { asm volatile("cp.async.commit_group;" ::: "memory"); }
__device__ __forceinline__ void cp_wait0()  { asm volatile("cp.async.wait_group 0;" ::: "memory"); }
__device__ __forceinline__ void cp_wait1()  { asm volatile("cp.async.wait_group 1;" ::: "memory"); }

#define MMAF16(d, a, b0, b1) \
    asm volatile("mma.sync.aligned.m16n8k16.row.col.f32.f16.f16.f32 " \
        "{%0,%1,%2,%3}, {%4,%5,%6,%7}, {%8,%9}, {%0,%1,%2,%3};" \
        : "+f"((d)[0]), "+f"((d)[1]), "+f"((d)[2]), "+f"((d)[3]) \
        : "r"((a)[0]), "r"((a)[1]), "r"((a)[2]), "r"((a)[3]), "r"(b0), "r"(b1))

#define LDMX4(r, addr) \
    asm volatile("ldmatrix.sync.aligned.m8n8.x4.shared.b16 {%0,%1,%2,%3}, [%4];" \
        : "=r"((r)[0]), "=r"((r)[1]), "=r"((r)[2]), "=r"((r)[3]) : "r"(addr))

// ===================== scratch (static device globals) =====================
__device__ float g_q[MM * DD];
__device__ float g_k[MM * DD];
__device__ float g_v[MM * DD];
__device__ float g_attn[MM * DD];
__device__ float g_out1[MM * DD];
__device__ float g_Gpart[BB * HH * 8 * DH * DH];
__device__ float g_Wt[BB * HH * DH * DH];
__device__ double g_part[4096][2];
__device__ double g_red[2];

// fp16 operands
__device__ __half g_xf[MM * DD];
__device__ __half g_apf[MM * DD];          // attnpre (weighted V) in fp16
__device__ __half g_wqf[DD * DD];
__device__ __half g_wkf[DD * DD];
__device__ __half g_wvf[DD * DD];
__device__ __half g_wof[DD * DD];
__device__ __half g_w1f[FF * DD];
__device__ __half g_w2f[DD * FF];
__device__ __half g_atf[MM * DD];
__device__ __half g_hf[(size_t)MM * FF];

// ===================== fp32 -> fp16 convert =====================
__global__ void __launch_bounds__(256) cvtf16_kernel(
    const float* __restrict__ src, __half* __restrict__ dst, size_t n4)
{
    const size_t stride = (size_t)gridDim.x * blockDim.x;
    for (size_t i4 = (size_t)blockIdx.x * blockDim.x + threadIdx.x; i4 < n4; i4 += stride) {
        float4 v = ((const float4*)src)[i4];
        ((__half2*)dst)[i4 * 2 + 0] = __floats2half2_rn(v.x, v.y);
        ((__half2*)dst)[i4 * 2 + 1] = __floats2half2_rn(v.z, v.w);
    }
}

// ===================== fp16 single-product HMMA GEMM =====================
// C[m,n] = sum_k A[m,k]*B[n,k] + bias[n] (+res)(+gelu); fp32 accum
#define GW_BM 128
#define GW_BN 128
#define GW_BK 32
#define ROWB 80
#define BUFB (128 * ROWB)
#define F16_STAGEB (2 * BUFB)
#define F16_SMEM (2 * F16_STAGEB)   // 40960

template <bool HAS_RES, bool GELU, bool OUTF16>
__global__ void __launch_bounds__(256, 2) gemm_f16(
    const __half* __restrict__ A, const __half* __restrict__ B,
    const float* __restrict__ bias, const float* __restrict__ res,
    float* __restrict__ Cf, __half* __restrict__ Ch,
    int M, int N, int K)
{
    extern __shared__ char sm[];
    const int tid = threadIdx.x;
    const int wid = tid >> 5;
    const int lane = tid & 31;
    const int wm = wid & 3;
    const int wn = wid >> 2;
    const int bm = blockIdx.y * GW_BM;
    const int bn = blockIdx.x * GW_BN;
    const int KT = K / GW_BK;
    const uint32_t smb = smem_u32(sm);

    auto load_stage = [&](int kt, uint32_t sb) {
        const int k0 = kt * GW_BK;
#pragma unroll
        for (int i = 0; i < 4; i++) {
            const int c = tid + i * 256;
            const int buf = c >> 9;
            const int cc = c & 511;
            const int row = cc >> 2;
            const int qq = cc & 3;
            const __half* gb = buf ? B : A;
            const int grow = (buf ? bn : bm) + row;
            const void* src = gb + (size_t)grow * K + k0 + qq * 8;
            cp_async16(sb + buf * BUFB + row * ROWB + qq * 16, src);
        }
    };

    float acc[2][8][4];
#pragma unroll
    for (int mt = 0; mt < 2; mt++)
#pragma unroll
        for (int nt = 0; nt < 8; nt++)
#pragma unroll
            for (int r = 0; r < 4; r++) acc[mt][nt][r] = 0.0f;

    load_stage(0, smb);
    cp_commit();

    const int lr = lane & 7;
    const int a_row = wm * 32 + lr + ((lane & 8) ? 8 : 0);
    const int a_kb  = (lane & 16) ? 16 : 0;
    const int b_row = wn * 64 + lr + ((lane & 16) ? 8 : 0);
    const int b_kb  = (lane & 8) ? 16 : 0;

    for (int kt = 0; kt < KT; kt++) {
        const uint32_t sb = smb + (uint32_t)(kt & 1) * F16_STAGEB;
        if (kt + 1 < KT) {
            load_stage(kt + 1, smb + (uint32_t)((kt + 1) & 1) * F16_STAGEB);
            cp_commit();
            cp_wait1();
        } else {
            cp_wait0();
        }
        __syncthreads();

        const uint32_t As = sb;
        const uint32_t Bs = sb + BUFB;

#pragma unroll
        for (int k16 = 0; k16 < 2; k16++) {
            const int kc = k16 * 32;
            uint32_t af[2][4];
#pragma unroll
            for (int mt = 0; mt < 2; mt++)
                LDMX4(af[mt], As + (uint32_t)((a_row + mt * 16) * ROWB + kc + a_kb));
#pragma unroll
            for (int p = 0; p < 4; p++) {
                uint32_t bf[4];
                LDMX4(bf, Bs + (uint32_t)((b_row + p * 16) * ROWB + kc + b_kb));
#pragma unroll
                for (int sub = 0; sub < 2; sub++) {
                    const int nt = p * 2 + sub;
#pragma unroll
                    for (int mt = 0; mt < 2; mt++)
                        MMAF16(acc[mt][nt], af[mt], bf[sub * 2], bf[sub * 2 + 1]);
                }
            }
        }
        __syncthreads();
    }

#pragma unroll
    for (int mt = 0; mt < 2; mt++) {
        const int r0 = bm + wm * 32 + mt * 16 + (lane >> 2);
#pragma unroll
        for (int nt = 0; nt < 8; nt++) {
            const int c = bn + wn * 64 + nt * 8 + ((lane & 3) << 1);
            const float b0 = bias[c], b1 = bias[c + 1];
#pragma unroll
            for (int half = 0; half < 2; half++) {
                const int row = r0 + half * 8;
                float v0 = acc[mt][nt][half * 2 + 0] + b0;
                float v1 = acc[mt][nt][half * 2 + 1] + b1;
                if (HAS_RES) {
                    const float2 rr = *(const float2*)(res + (size_t)row * N + c);
                    v0 += rr.x; v1 += rr.y;
                }
                if (GELU) {
                    v0 = 0.5f * v0 * (1.0f + erff(v0 * 0.70710678118654752f));
                    v1 = 0.5f * v1 * (1.0f + erff(v1 * 0.70710678118654752f));
                }
                if (OUTF16) {
                    *(__half2*)(Ch + (size_t)row * N + c) = __floats2half2_rn(v0, v1);
                } else {
                    float2 o; o.x = v0; o.y = v1;
                    *(float2*)(Cf + (size_t)row * N + c) = o;
                }
            }
        }
    }
}

// ===================== attention small ops (R5-verified) =====================
__global__ void __launch_bounds__(256) gram_kernel(
    const float* __restrict__ q, const float* __restrict__ k,
    float* __restrict__ Gpart)
{
    const int bh = blockIdx.x;
    const int ns = blockIdx.y;
    const int b = bh >> 4, h = bh & 15;
    const int tid = threadIdx.x;
    __shared__ float Qs[32][68];
    __shared__ float Ks[32][68];

    float acc[4][4];
#pragma unroll
    for (int i = 0; i < 4; i++)
#pragma unroll
        for (int j = 0; j < 4; j++) acc[i][j] = 0.0f;

    const int ty = tid >> 4, tx = tid & 15;
    const size_t base = ((size_t)b * NN) * DD + h * DH;
    const int n0s = ns * 512;

    for (int n0 = n0s; n0 < n0s + 512; n0 += 32) {
#pragma unroll
        for (int r = 0; r < 2; r++) {
            int idx4 = tid + r * 256;
            int nn = idx4 >> 4;
            int i4 = (idx4 & 15) * 4;
            float4 qv = *(const float4*)(q + base + (size_t)(n0 + nn) * DD + i4);
            float4 kv = *(const float4*)(k + base + (size_t)(n0 + nn) * DD + i4);
            *(float4*)&Qs[nn][i4] = qv;
            *(float4*)&Ks[nn][i4] = kv;
        }
        __syncthreads();
#pragma unroll
        for (int kk = 0; kk < 32; kk++) {
            float qr[4], kr[4];
#pragma unroll
            for (int i = 0; i < 4; i++) qr[i] = Qs[kk][ty * 4 + i];
#pragma unroll
            for (int j = 0; j < 4; j++) kr[j] = Ks[kk][tx * 4 + j];
#pragma unroll
            for (int i = 0; i < 4; i++)
#pragma unroll
                for (int j = 0; j < 4; j++) acc[i][j] += qr[i] * kr[j];
        }
        __syncthreads();
    }

    float* Gout = Gpart + ((size_t)bh * 8 + ns) * (DH * DH);
#pragma unroll
    for (int i = 0; i < 4; i++)
#pragma unroll
        for (int j = 0; j < 4; j++)
            Gout[(ty * 4 + i) * DH + tx * 4 + j] = acc[i][j];
}

__global__ void __launch_bounds__(256) weights_kernel(
    const float* __restrict__ Gpart, float* __restrict__ Wt)
{
    const int bh = blockIdx.x;
    const int tid = threadIdx.x;
    __shared__ float Gs[DH][DH];
    __shared__ float ct[DH], st[DH];

    for (int e = tid; e < DH * DH; e += 256) {
        float sacc = 0.0f;
#pragma unroll
        for (int p = 0; p < 8; p++)
            sacc += Gpart[((size_t)bh * 8 + p) * (DH * DH) + e];
        Gs[e >> 6][e & 63] = sacc;
    }
    if (tid < DH) {
        float a = 6.283185307179586f * (float)tid / 64.0f;
        ct[tid] = cosf(a);
        st[tid] = sinf(a);
    }
    __syncthreads();

    const int i = tid >> 2;
    const int j0 = (tid & 3) * 16;
    for (int jj = 0; jj < 16; jj++) {
        const int j = j0 + jj;
        float re = 0.0f, im = 0.0f;
#pragma unroll
        for (int kk = 0; kk < DH; kk++) {
            const int t = (kk * j) & 63;
            const float g = Gs[i][kk];
            re += g * ct[t];
            im += g * st[t];
        }
        Wt[(size_t)bh * (DH * DH) + i * DH + j] = sqrtf(re * re + im * im);
    }
}

// attnpre = weights @ v per (b,h), written directly as fp16 for the O projection
__global__ void __launch_bounds__(256) applyw_kernel(
    const float* __restrict__ v, const float* __restrict__ Wt,
    __half* __restrict__ ohf)
{
    const int bh = blockIdx.x;
    const int b = bh >> 4, h = bh & 15;
    const int tid = threadIdx.x;
    __shared__ float Ws[DH][DH + 1];
    __shared__ float Vs[4][DH];

    for (int e = tid; e < DH * DH; e += 256)
        Ws[e >> 6][e & 63] = Wt[(size_t)bh * (DH * DH) + e];
    __syncthreads();

    const int nn = tid >> 6;
    const int i = tid & 63;
    const size_t base = ((size_t)b * NN) * DD + h * DH;
    const int n0 = blockIdx.y * 64;

    for (int n = n0; n < n0 + 64; n += 4) {
        Vs[nn][i] = v[base + (size_t)(n + nn) * DD + i];
        __syncthreads();
        float acc = 0.0f;
#pragma unroll
        for (int j = 0; j < DH; j++) acc += Ws[i][j] * Vs[nn][j];
        ohf[base + (size_t)(n + nn) * DD + i] = __float2half(acc);
        __syncthreads();
    }
}

// ===================== global-std reduction + norm =====================
__global__ void __launch_bounds__(256) red1_kernel(const float* __restrict__ x, size_t n)
{
    float s = 0.0f, s2 = 0.0f;
    const size_t stride = (size_t)gridDim.x * blockDim.x;
    for (size_t idx = (size_t)blockIdx.x * blockDim.x + threadIdx.x; idx < n; idx += stride) {
        const float vv = x[idx];
        s += vv;
        s2 += vv * vv;
    }
#pragma unroll
    for (int o = 16; o > 0; o >>= 1) {
        s += __shfl_down_sync(0xFFFFFFFFu, s, o);
        s2 += __shfl_down_sync(0xFFFFFFFFu, s2, o);
    }
    __shared__ double sh[2][8];
    const int w = threadIdx.x >> 5, l = threadIdx.x & 31;
    if (l == 0) { sh[0][w] = (double)s; sh[1][w] = (double)s2; }
    __syncthreads();
    if (threadIdx.x == 0) {
        double a = 0.0, b = 0.0;
#pragma unroll
        for (int i = 0; i < 8; i++) { a += sh[0][i]; b += sh[1][i]; }
        g_part[blockIdx.x][0] = a;
        g_part[blockIdx.x][1] = b;
    }
}

__global__ void __launch_bounds__(256) red2_kernel(int nb)
{
    double a = 0.0, b = 0.0;
    for (int i = threadIdx.x; i < nb; i += 256) { a += g_part[i][0]; b += g_part[i][1]; }
    __shared__ double sa[256], sb[256];
    sa[threadIdx.x] = a;
    sb[threadIdx.x] = b;
    __syncthreads();
    for (int o = 128; o > 0; o >>= 1) {
        if (threadIdx.x < o) { sa[threadIdx.x] += sa[threadIdx.x + o]; sb[threadIdx.x] += sb[threadIdx.x + o]; }
        __syncthreads();
    }
    if (threadIdx.x == 0) { g_red[0] = sa[0]; g_red[1] = sb[0]; }
}

template <int OUTK> // 0 = fp32 only, 2 = also fp16
__global__ void __launch_bounds__(256) norm_kernel(
    const float* __restrict__ x, const float* __restrict__ alpha,
    const float* __restrict__ beta, const float* __restrict__ eps,
    float* __restrict__ y, __half* __restrict__ yh, size_t n)
{
    const double Md = (double)n;
    const double mean = g_red[0] / Md;
    const double var = (g_red[1] - Md * mean * mean) / (Md - 1.0);
    const float sd = (float)sqrt(var);

    const size_t n4 = n >> 2;
    const size_t stride = (size_t)gridDim.x * blockDim.x;
    for (size_t i4 = (size_t)blockIdx.x * blockDim.x + threadIdx.x; i4 < n4; i4 += stride) {
        float4 v = ((const float4*)x)[i4];
        const int d = (int)((i4 * 4) & (DD - 1));
        v.x = v.x / (sd + eps[d + 0]) * alpha[d + 0] + beta[d + 0];
        v.y = v.y / (sd + eps[d + 1]) * alpha[d + 1] + beta[d + 1];
        v.z = v.z / (sd + eps[d + 2]) * alpha[d + 2] + beta[d + 2];
        v.w = v.w / (sd + eps[d + 3]) * alpha[d + 3] + beta[d + 3];
        ((float4*)y)[i4] = v;
        if (OUTK == 2) {
            ((__half2*)yh)[i4 * 2 + 0] = __floats2half2_rn(v.x, v.y);
            ((__half2*)yh)[i4 * 2 + 1] = __floats2half2_rn(v.z, v.w);
        }
    }
}

// ===================== launch =====================
extern "C" void kernel_launch(void* const* d_in, const int* in_sizes, int n_in,
                              void* d_out, int out_size)
{
    const float* x    = (const float*)d_in[0];
    const float* wq_w = (const float*)d_in[1];
    const float* wq_b = (const float*)d_in[2];
    const float* wk_w = (const float*)d_in[3];
    const float* wk_b = (const float*)d_in[4];
    const float* wv_w = (const float*)d_in[5];
    const float* wv_b = (const float*)d_in[6];
    const float* wo_w = (const float*)d_in[7];
    const float* wo_b = (const float*)d_in[8];
    const float* w1   = (const float*)d_in[9];
    const float* b1   = (const float*)d_in[10];
    const float* w2   = (const float*)d_in[11];
    const float* b2   = (const float*)d_in[12];
    const float* an_a = (const float*)d_in[13];
    const float* an_b = (const float*)d_in[14];
    const float* an_e = (const float*)d_in[15];
    const float* mn_a = (const float*)d_in[16];
    const float* mn_b = (const float*)d_in[17];
    const float* mn_e = (const float*)d_in[18];
    float* out = (float*)d_out;

    float *q, *k, *v, *attn, *out1, *Gpart, *Wt;
    cudaGetSymbolAddress((void**)&q, g_q);
    cudaGetSymbolAddress((void**)&k, g_k);
    cudaGetSymbolAddress((void**)&v, g_v);
    cudaGetSymbolAddress((void**)&attn, g_attn);
    cudaGetSymbolAddress((void**)&out1, g_out1);
    cudaGetSymbolAddress((void**)&Gpart, g_Gpart);
    cudaGetSymbolAddress((void**)&Wt, g_Wt);

    __half *xf, *apf, *wqf, *wkf, *wvf, *wof, *w1f, *w2f, *atf, *hf;
    cudaGetSymbolAddress((void**)&xf, g_xf);
    cudaGetSymbolAddress((void**)&apf, g_apf);
    cudaGetSymbolAddress((void**)&wqf, g_wqf);
    cudaGetSymbolAddress((void**)&wkf, g_wkf);
    cudaGetSymbolAddress((void**)&wvf, g_wvf);
    cudaGetSymbolAddress((void**)&wof, g_wof);
    cudaGetSymbolAddress((void**)&w1f, g_w1f);
    cudaGetSymbolAddress((void**)&w2f, g_w2f);
    cudaGetSymbolAddress((void**)&atf, g_atf);
    cudaGetSymbolAddress((void**)&hf, g_hf);

    cudaFuncSetAttribute(gemm_f16<false, false, false>, cudaFuncAttributeMaxDynamicSharedMemorySize, F16_SMEM);
    cudaFuncSetAttribute(gemm_f16<true,  false, false>, cudaFuncAttributeMaxDynamicSharedMemorySize, F16_SMEM);
    cudaFuncSetAttribute(gemm_f16<false, true,  true >, cudaFuncAttributeMaxDynamicSharedMemorySize, F16_SMEM);

    // ---- conversions to fp16 ----
    cvtf16_kernel<<<1024, 256>>>(x, xf, TOT / 4);
    cvtf16_kernel<<<512, 256>>>(wq_w, wqf, (size_t)DD * DD / 4);
    cvtf16_kernel<<<512, 256>>>(wk_w, wkf, (size_t)DD * DD / 4);
    cvtf16_kernel<<<512, 256>>>(wv_w, wvf, (size_t)DD * DD / 4);
    cvtf16_kernel<<<512, 256>>>(wo_w, wof, (size_t)DD * DD / 4);
    cvtf16_kernel<<<1024, 256>>>(w1, w1f, (size_t)FF * DD / 4);
    cvtf16_kernel<<<1024, 256>>>(w2, w2f, (size_t)DD * FF / 4);

    const dim3 gProj(DD / GW_BN, MM / GW_BM);   // (8, 128)
    const dim3 gMlp1(FF / GW_BN, MM / GW_BM);   // (32, 128)

    // ---- Q/K/V projections (fp16, fp32 accum) ----
    gemm_f16<false, false, false><<<gProj, 256, F16_SMEM>>>(xf, wqf, wq_b, nullptr, q, nullptr, MM, DD, DD);
    gemm_f16<false, false, false><<<gProj, 256, F16_SMEM>>>(xf, wkf, wk_b, nullptr, k, nullptr, MM, DD, DD);
    gemm_f16<false, false, false><<<gProj, 256, F16_SMEM>>>(xf, wvf, wv_b, nullptr, v, nullptr, MM, DD, DD);

    // ---- FFT attention (collapsed form) ----
    gram_kernel<<<dim3(BB * HH, 8), 256>>>(q, k, Gpart);
    weights_kernel<<<BB * HH, 256>>>(Gpart, Wt);
    applyw_kernel<<<dim3(BB * HH, NN / 64), 256>>>(v, Wt, apf);

    // ---- output projection + residual ----
    gemm_f16<true, false, false><<<gProj, 256, F16_SMEM>>>(apf, wof, wo_b, x, attn, nullptr, MM, DD, DD);

    // ---- rmsnorm 1 (global std), also emits fp16 for MLP1 ----
    red1_kernel<<<2048, 256>>>(attn, TOT);
    red2_kernel<<<1, 256>>>(2048);
    norm_kernel<2><<<2048, 256>>>(attn, an_a, an_b, an_e, attn, atf, TOT);

    // ---- MLP (fp16) ----
    gemm_f16<false, true, true><<<gMlp1, 256, F16_SMEM>>>(atf, w1f, b1, nullptr, nullptr, hf, MM, FF, DD);
    gemm_f16<true, false, false><<<gProj, 256, F16_SMEM>>>(hf, w2f, b2, attn, out1, nullptr, MM, DD, FF);

    // ---- rmsnorm 2 -> final output ----
    red1_kernel<<<2048, 256>>>(out1, TOT);
    red2_kernel<<<1, 256>>>(2048);
    norm_kernel<0><<<2048, 256>>>(out1, mn_a, mn_b, mn_e, out, nullptr, TOT);
}

// round 11
// speedup vs baseline: 1.6422x; 1.0110x over previous
#include <cuda_runtime.h>
#include <cuda_fp16.h>
#include <cstdint>
#include <math.h>

// Problem dims (fixed by the dataset)
#define BB 4
#define NN 4096
#define DD 1024
#define HH 16
#define DH 64
#define FF 4096
#define MM (BB * NN)          // 16384
#define TOT ((size_t)MM * DD) // 16,777,216

// ===================== helpers =====================
__device__ __forceinline__ uint32_t smem_u32(const void* p) {
    uint32_t a;
    asm("{ .reg .u64 t; cvta.to.shared.u64 t, %1; cvt.u32.u64 %0, t; }" : "=r"(a) : "l"(p));
    return a;
}
__device__ __forceinline__ void cp_async16(uint32_t dst, const void* src) {
    asm volatile("cp.async.cg.shared.global [%0], [%1], 16;"
                 :: "r"(dst), "l"(__cvta_generic_to_global(src)));
}
__device__ __forceinline__ void cp_commit() { asm volatile("cp.async.commit_group;" ::: "memory"); }
__device__ __forceinline__ void cp_wait0()  { asm volatile("cp.async.wait_group 0;" ::: "memory"); }
__device__ __forceinline__ void cp_wait1()  { asm volatile("cp.async.wait_group 1;" ::: "memory"); }

#define MMAF16(d, a, b0, b1) \
    asm volatile("mma.sync.aligned.m16n8k16.row.col.f32.f16.f16.f32 " \
        "{%0,%1,%2,%3}, {%4,%5,%6,%7}, {%8,%9}, {%0,%1,%2,%3};" \
        : "+f"((d)[0]), "+f"((d)[1]), "+f"((d)[2]), "+f"((d)[3]) \
        : "r"((a)[0]), "r"((a)[1]), "r"((a)[2]), "r"((a)[3]), "r"(b0), "r"(b1))

#define LDMX4(r, addr) \
    asm volatile("ldmatrix.sync.aligned.m8n8.x4.shared.b16 {%0,%1,%2,%3}, [%4];" \
        : "=r"((r)[0]), "=r"((r)[1]), "=r"((r)[2]), "=r"((r)[3]) : "r"(addr))

// ===================== scratch (static device globals) =====================
__device__ float g_q[MM * DD];
__device__ float g_k[MM * DD];
__device__ float g_v[MM * DD];
__device__ float g_attn[MM * DD];
__device__ float g_out1[MM * DD];
__device__ float g_Gpart[BB * HH * 8 * DH * DH];
__device__ float g_Wt[BB * HH * DH * DH];
__device__ double g_part[4096][2];
__device__ double g_red[2];

// fp16 operands
__device__ __half g_xf[MM * DD];
__device__ __half g_apf[MM * DD];          // attnpre (weighted V) in fp16
__device__ __half g_wqf[DD * DD];
__device__ __half g_wkf[DD * DD];
__device__ __half g_wvf[DD * DD];
__device__ __half g_wof[DD * DD];
__device__ __half g_w1f[FF * DD];
__device__ __half g_w2f[DD * FF];
__device__ __half g_atf[MM * DD];
__device__ __half g_hf[(size_t)MM * FF];

// ===================== fp32 -> fp16 convert =====================
__global__ void __launch_bounds__(256) cvtf16_kernel(
    const float* __restrict__ src, __half* __restrict__ dst, size_t n4)
{
    const size_t stride = (size_t)gridDim.x * blockDim.x;
    for (size_t i4 = (size_t)blockIdx.x * blockDim.x + threadIdx.x; i4 < n4; i4 += stride) {
        float4 v = ((const float4*)src)[i4];
        ((__half2*)dst)[i4 * 2 + 0] = __floats2half2_rn(v.x, v.y);
        ((__half2*)dst)[i4 * 2 + 1] = __floats2half2_rn(v.z, v.w);
    }
}

// ===================== fp16 single-product HMMA GEMM =====================
// C[m,n] = sum_k A[m,k]*B[n,k] + bias[n] (+res)(+gelu); fp32 accum.
// Optional fused sum/sumsq reduction of output values into g_part[cta].
#define GW_BM 128
#define GW_BN 128
#define GW_BK 32
#define ROWB 80
#define BUFB (128 * ROWB)
#define F16_STAGEB (2 * BUFB)          // 20480 per stage (A + B)
#define NSTAGE 3
#define F16_SMEM (NSTAGE * F16_STAGEB) // 61440

template <bool HAS_RES, bool GELU, bool OUTF16, bool DO_RED>
__global__ void __launch_bounds__(256, 2) gemm_f16(
    const __half* __restrict__ A, const __half* __restrict__ B,
    const float* __restrict__ bias, const float* __restrict__ res,
    float* __restrict__ Cf, __half* __restrict__ Ch,
    int M, int N, int K)
{
    extern __shared__ char sm[];
    const int tid = threadIdx.x;
    const int wid = tid >> 5;
    const int lane = tid & 31;
    const int wm = wid & 3;
    const int wn = wid >> 2;
    const int bm = blockIdx.y * GW_BM;
    const int bn = blockIdx.x * GW_BN;
    const int KT = K / GW_BK;
    const uint32_t smb = smem_u32(sm);

    auto load_stage = [&](int kt) {
        const uint32_t sb = smb + (uint32_t)(kt % NSTAGE) * F16_STAGEB;
        const int k0 = kt * GW_BK;
#pragma unroll
        for (int i = 0; i < 4; i++) {
            const int c = tid + i * 256;
            const int buf = c >> 9;
            const int cc = c & 511;
            const int row = cc >> 2;
            const int qq = cc & 3;
            const __half* gb = buf ? B : A;
            const int grow = (buf ? bn : bm) + row;
            const void* src = gb + (size_t)grow * K + k0 + qq * 8;
            cp_async16(sb + buf * BUFB + row * ROWB + qq * 16, src);
        }
    };

    float acc[2][8][4];
#pragma unroll
    for (int mt = 0; mt < 2; mt++)
#pragma unroll
        for (int nt = 0; nt < 8; nt++)
#pragma unroll
            for (int r = 0; r < 4; r++) acc[mt][nt][r] = 0.0f;

    // prologue: 2 stages in flight
    load_stage(0);
    cp_commit();
    if (KT > 1) { load_stage(1); cp_commit(); }

    const int lr = lane & 7;
    const int a_row = wm * 32 + lr + ((lane & 8) ? 8 : 0);
    const int a_kb  = (lane & 16) ? 16 : 0;
    const int b_row = wn * 64 + lr + ((lane & 16) ? 8 : 0);
    const int b_kb  = (lane & 8) ? 16 : 0;

    for (int kt = 0; kt < KT; kt++) {
        // ensure stage kt's loads have landed (≤1 younger group may remain in flight)
        if (kt + 1 < KT) cp_wait1(); else cp_wait0();
        __syncthreads();

        // issue loads 2 stages ahead into the buffer freed by iteration kt-1
        if (kt + 2 < KT) {
            load_stage(kt + 2);
            cp_commit();
        }

        const uint32_t sb = smb + (uint32_t)(kt % NSTAGE) * F16_STAGEB;
        const uint32_t As = sb;
        const uint32_t Bs = sb + BUFB;

#pragma unroll
        for (int k16 = 0; k16 < 2; k16++) {
            const int kc = k16 * 32;
            uint32_t af[2][4];
#pragma unroll
            for (int mt = 0; mt < 2; mt++)
                LDMX4(af[mt], As + (uint32_t)((a_row + mt * 16) * ROWB + kc + a_kb));
#pragma unroll
            for (int p = 0; p < 4; p++) {
                uint32_t bf[4];
                LDMX4(bf, Bs + (uint32_t)((b_row + p * 16) * ROWB + kc + b_kb));
#pragma unroll
                for (int sub = 0; sub < 2; sub++) {
                    const int nt = p * 2 + sub;
#pragma unroll
                    for (int mt = 0; mt < 2; mt++)
                        MMAF16(acc[mt][nt], af[mt], bf[sub * 2], bf[sub * 2 + 1]);
                }
            }
        }
        __syncthreads();
    }

    float rs = 0.0f, rs2 = 0.0f;

#pragma unroll
    for (int mt = 0; mt < 2; mt++) {
        const int r0 = bm + wm * 32 + mt * 16 + (lane >> 2);
#pragma unroll
        for (int nt = 0; nt < 8; nt++) {
            const int c = bn + wn * 64 + nt * 8 + ((lane & 3) << 1);
            const float b0 = bias[c], b1 = bias[c + 1];
#pragma unroll
            for (int half = 0; half < 2; half++) {
                const int row = r0 + half * 8;
                float v0 = acc[mt][nt][half * 2 + 0] + b0;
                float v1 = acc[mt][nt][half * 2 + 1] + b1;
                if (HAS_RES) {
                    const float2 rr = *(const float2*)(res + (size_t)row * N + c);
                    v0 += rr.x; v1 += rr.y;
                }
                if (GELU) {
                    v0 = 0.5f * v0 * (1.0f + erff(v0 * 0.70710678118654752f));
                    v1 = 0.5f * v1 * (1.0f + erff(v1 * 0.70710678118654752f));
                }
                if (DO_RED) {
                    rs += v0 + v1;
                    rs2 += v0 * v0 + v1 * v1;
                }
                if (OUTF16) {
                    *(__half2*)(Ch + (size_t)row * N + c) = __floats2half2_rn(v0, v1);
                } else {
                    float2 o; o.x = v0; o.y = v1;
                    *(float2*)(Cf + (size_t)row * N + c) = o;
                }
            }
        }
    }

    if (DO_RED) {
#pragma unroll
        for (int o = 16; o > 0; o >>= 1) {
            rs += __shfl_down_sync(0xFFFFFFFFu, rs, o);
            rs2 += __shfl_down_sync(0xFFFFFFFFu, rs2, o);
        }
        __shared__ float shr[2][8];
        if (lane == 0) { shr[0][wid] = rs; shr[1][wid] = rs2; }
        __syncthreads();
        if (tid == 0) {
            double a = 0.0, b = 0.0;
#pragma unroll
            for (int i = 0; i < 8; i++) { a += (double)shr[0][i]; b += (double)shr[1][i]; }
            const int cid = blockIdx.y * gridDim.x + blockIdx.x;
            g_part[cid][0] = a;
            g_part[cid][1] = b;
        }
    }
}

// ===================== attention small ops (R5-verified) =====================
__global__ void __launch_bounds__(256) gram_kernel(
    const float* __restrict__ q, const float* __restrict__ k,
    float* __restrict__ Gpart)
{
    const int bh = blockIdx.x;
    const int ns = blockIdx.y;
    const int b = bh >> 4, h = bh & 15;
    const int tid = threadIdx.x;
    __shared__ float Qs[32][68];
    __shared__ float Ks[32][68];

    float acc[4][4];
#pragma unroll
    for (int i = 0; i < 4; i++)
#pragma unroll
        for (int j = 0; j < 4; j++) acc[i][j] = 0.0f;

    const int ty = tid >> 4, tx = tid & 15;
    const size_t base = ((size_t)b * NN) * DD + h * DH;
    const int n0s = ns * 512;

    for (int n0 = n0s; n0 < n0s + 512; n0 += 32) {
#pragma unroll
        for (int r = 0; r < 2; r++) {
            int idx4 = tid + r * 256;
            int nn = idx4 >> 4;
            int i4 = (idx4 & 15) * 4;
            float4 qv = *(const float4*)(q + base + (size_t)(n0 + nn) * DD + i4);
            float4 kv = *(const float4*)(k + base + (size_t)(n0 + nn) * DD + i4);
            *(float4*)&Qs[nn][i4] = qv;
            *(float4*)&Ks[nn][i4] = kv;
        }
        __syncthreads();
#pragma unroll
        for (int kk = 0; kk < 32; kk++) {
            float qr[4], kr[4];
#pragma unroll
            for (int i = 0; i < 4; i++) qr[i] = Qs[kk][ty * 4 + i];
#pragma unroll
            for (int j = 0; j < 4; j++) kr[j] = Ks[kk][tx * 4 + j];
#pragma unroll
            for (int i = 0; i < 4; i++)
#pragma unroll
                for (int j = 0; j < 4; j++) acc[i][j] += qr[i] * kr[j];
        }
        __syncthreads();
    }

    float* Gout = Gpart + ((size_t)bh * 8 + ns) * (DH * DH);
#pragma unroll
    for (int i = 0; i < 4; i++)
#pragma unroll
        for (int j = 0; j < 4; j++)
            Gout[(ty * 4 + i) * DH + tx * 4 + j] = acc[i][j];
}

__global__ void __launch_bounds__(256) weights_kernel(
    const float* __restrict__ Gpart, float* __restrict__ Wt)
{
    const int bh = blockIdx.x;
    const int tid = threadIdx.x;
    __shared__ float Gs[DH][DH];
    __shared__ float ct[DH], st[DH];

    for (int e = tid; e < DH * DH; e += 256) {
        float sacc = 0.0f;
#pragma unroll
        for (int p = 0; p < 8; p++)
            sacc += Gpart[((size_t)bh * 8 + p) * (DH * DH) + e];
        Gs[e >> 6][e & 63] = sacc;
    }
    if (tid < DH) {
        float a = 6.283185307179586f * (float)tid / 64.0f;
        ct[tid] = cosf(a);
        st[tid] = sinf(a);
    }
    __syncthreads();

    const int i = tid >> 2;
    const int j0 = (tid & 3) * 16;
    for (int jj = 0; jj < 16; jj++) {
        const int j = j0 + jj;
        float re = 0.0f, im = 0.0f;
#pragma unroll
        for (int kk = 0; kk < DH; kk++) {
            const int t = (kk * j) & 63;
            const float g = Gs[i][kk];
            re += g * ct[t];
            im += g * st[t];
        }
        Wt[(size_t)bh * (DH * DH) + i * DH + j] = sqrtf(re * re + im * im);
    }
}

// attnpre = weights @ v per (b,h), written directly as fp16 for the O projection
__global__ void __launch_bounds__(256) applyw_kernel(
    const float* __restrict__ v, const float* __restrict__ Wt,
    __half* __restrict__ ohf)
{
    const int bh = blockIdx.x;
    const int b = bh >> 4, h = bh & 15;
    const int tid = threadIdx.x;
    __shared__ float Ws[DH][DH + 1];
    __shared__ float Vs[4][DH];

    for (int e = tid; e < DH * DH; e += 256)
        Ws[e >> 6][e & 63] = Wt[(size_t)bh * (DH * DH) + e];
    __syncthreads();

    const int nn = tid >> 6;
    const int i = tid & 63;
    const size_t base = ((size_t)b * NN) * DD + h * DH;
    const int n0 = blockIdx.y * 64;

    for (int n = n0; n < n0 + 64; n += 4) {
        Vs[nn][i] = v[base + (size_t)(n + nn) * DD + i];
        __syncthreads();
        float acc = 0.0f;
#pragma unroll
        for (int j = 0; j < DH; j++) acc += Ws[i][j] * Vs[nn][j];
        ohf[base + (size_t)(n + nn) * DD + i] = __float2half(acc);
        __syncthreads();
    }
}

// ===================== reduction finalize + norm =====================
__global__ void __launch_bounds__(256) red2_kernel(int nb)
{
    double a = 0.0, b = 0.0;
    for (int i = threadIdx.x; i < nb; i += 256) { a += g_part[i][0]; b += g_part[i][1]; }
    __shared__ double sa[256], sb[256];
    sa[threadIdx.x] = a;
    sb[threadIdx.x] = b;
    __syncthreads();
    for (int o = 128; o > 0; o >>= 1) {
        if (threadIdx.x < o) { sa[threadIdx.x] += sa[threadIdx.x + o]; sb[threadIdx.x] += sb[threadIdx.x + o]; }
        __syncthreads();
    }
    if (threadIdx.x == 0) { g_red[0] = sa[0]; g_red[1] = sb[0]; }
}

template <int OUTK> // 0 = fp32 only, 2 = also fp16
__global__ void __launch_bounds__(256) norm_kernel(
    const float* __restrict__ x, const float* __restrict__ alpha,
    const float* __restrict__ beta, const float* __restrict__ eps,
    float* __restrict__ y, __half* __restrict__ yh, size_t n)
{
    const double Md = (double)n;
    const double mean = g_red[0] / Md;
    const double var = (g_red[1] - Md * mean * mean) / (Md - 1.0);
    const float sd = (float)sqrt(var);

    const size_t n4 = n >> 2;
    const size_t stride = (size_t)gridDim.x * blockDim.x;
    for (size_t i4 = (size_t)blockIdx.x * blockDim.x + threadIdx.x; i4 < n4; i4 += stride) {
        float4 v = ((const float4*)x)[i4];
        const int d = (int)((i4 * 4) & (DD - 1));
        v.x = v.x / (sd + eps[d + 0]) * alpha[d + 0] + beta[d + 0];
        v.y = v.y / (sd + eps[d + 1]) * alpha[d + 1] + beta[d + 1];
        v.z = v.z / (sd + eps[d + 2]) * alpha[d + 2] + beta[d + 2];
        v.w = v.w / (sd + eps[d + 3]) * alpha[d + 3] + beta[d + 3];
        ((float4*)y)[i4] = v;
        if (OUTK == 2) {
            ((__half2*)yh)[i4 * 2 + 0] = __floats2half2_rn(v.x, v.y);
            ((__half2*)yh)[i4 * 2 + 1] = __floats2half2_rn(v.z, v.w);
        }
    }
}

// ===================== launch =====================
extern "C" void kernel_launch(void* const* d_in, const int* in_sizes, int n_in,
                              void* d_out, int out_size)
{
    const float* x    = (const float*)d_in[0];
    const float* wq_w = (const float*)d_in[1];
    const float* wq_b = (const float*)d_in[2];
    const float* wk_w = (const float*)d_in[3];
    const float* wk_b = (const float*)d_in[4];
    const float* wv_w = (const float*)d_in[5];
    const float* wv_b = (const float*)d_in[6];
    const float* wo_w = (const float*)d_in[7];
    const float* wo_b = (const float*)d_in[8];
    const float* w1   = (const float*)d_in[9];
    const float* b1   = (const float*)d_in[10];
    const float* w2   = (const float*)d_in[11];
    const float* b2   = (const float*)d_in[12];
    const float* an_a = (const float*)d_in[13];
    const float* an_b = (const float*)d_in[14];
    const float* an_e = (const float*)d_in[15];
    const float* mn_a = (const float*)d_in[16];
    const float* mn_b = (const float*)d_in[17];
    const float* mn_e = (const float*)d_in[18];
    float* out = (float*)d_out;

    float *q, *k, *v, *attn, *out1, *Gpart, *Wt;
    cudaGetSymbolAddress((void**)&q, g_q);
    cudaGetSymbolAddress((void**)&k, g_k);
    cudaGetSymbolAddress((void**)&v, g_v);
    cudaGetSymbolAddress((void**)&attn, g_attn);
    cudaGetSymbolAddress((void**)&out1, g_out1);
    cudaGetSymbolAddress((void**)&Gpart, g_Gpart);
    cudaGetSymbolAddress((void**)&Wt, g_Wt);

    __half *xf, *apf, *wqf, *wkf, *wvf, *wof, *w1f, *w2f, *atf, *hf;
    cudaGetSymbolAddress((void**)&xf, g_xf);
    cudaGetSymbolAddress((void**)&apf, g_apf);
    cudaGetSymbolAddress((void**)&wqf, g_wqf);
    cudaGetSymbolAddress((void**)&wkf, g_wkf);
    cudaGetSymbolAddress((void**)&wvf, g_wvf);
    cudaGetSymbolAddress((void**)&wof, g_wof);
    cudaGetSymbolAddress((void**)&w1f, g_w1f);
    cudaGetSymbolAddress((void**)&w2f, g_w2f);
    cudaGetSymbolAddress((void**)&atf, g_atf);
    cudaGetSymbolAddress((void**)&hf, g_hf);

    cudaFuncSetAttribute(gemm_f16<false, false, false, false>, cudaFuncAttributeMaxDynamicSharedMemorySize, F16_SMEM);
    cudaFuncSetAttribute(gemm_f16<true,  false, false, true >, cudaFuncAttributeMaxDynamicSharedMemorySize, F16_SMEM);
    cudaFuncSetAttribute(gemm_f16<false, true,  true,  false>, cudaFuncAttributeMaxDynamicSharedMemorySize, F16_SMEM);

    // ---- conversions to fp16 ----
    cvtf16_kernel<<<1024, 256>>>(x, xf, TOT / 4);
    cvtf16_kernel<<<512, 256>>>(wq_w, wqf, (size_t)DD * DD / 4);
    cvtf16_kernel<<<512, 256>>>(wk_w, wkf, (size_t)DD * DD / 4);
    cvtf16_kernel<<<512, 256>>>(wv_w, wvf, (size_t)DD * DD / 4);
    cvtf16_kernel<<<512, 256>>>(wo_w, wof, (size_t)DD * DD / 4);
    cvtf16_kernel<<<1024, 256>>>(w1, w1f, (size_t)FF * DD / 4);
    cvtf16_kernel<<<1024, 256>>>(w2, w2f, (size_t)DD * FF / 4);

    const dim3 gProj(DD / GW_BN, MM / GW_BM);   // (8, 128) -> 1024 CTAs
    const dim3 gMlp1(FF / GW_BN, MM / GW_BM);   // (32, 128)

    // ---- Q/K/V projections (fp16, fp32 accum) ----
    gemm_f16<false, false, false, false><<<gProj, 256, F16_SMEM>>>(xf, wqf, wq_b, nullptr, q, nullptr, MM, DD, DD);
    gemm_f16<false, false, false, false><<<gProj, 256, F16_SMEM>>>(xf, wkf, wk_b, nullptr, k, nullptr, MM, DD, DD);
    gemm_f16<false, false, false, false><<<gProj, 256, F16_SMEM>>>(xf, wvf, wv_b, nullptr, v, nullptr, MM, DD, DD);

    // ---- FFT attention (collapsed form) ----
    gram_kernel<<<dim3(BB * HH, 8), 256>>>(q, k, Gpart);
    weights_kernel<<<BB * HH, 256>>>(Gpart, Wt);
    applyw_kernel<<<dim3(BB * HH, NN / 64), 256>>>(v, Wt, apf);

    // ---- output projection + residual, with fused sum/sumsq reduction ----
    gemm_f16<true, false, false, true><<<gProj, 256, F16_SMEM>>>(apf, wof, wo_b, x, attn, nullptr, MM, DD, DD);

    // ---- rmsnorm 1 (global std from fused partials), also emits fp16 for MLP1 ----
    red2_kernel<<<1, 256>>>(1024);
    norm_kernel<2><<<2048, 256>>>(attn, an_a, an_b, an_e, attn, atf, TOT);

    // ---- MLP (fp16) ----
    gemm_f16<false, true, true, false><<<gMlp1, 256, F16_SMEM>>>(atf, w1f, b1, nullptr, nullptr, hf, MM, FF, DD);
    gemm_f16<true, false, false, true><<<gProj, 256, F16_SMEM>>>(hf, w2f, b2, attn, out1, nullptr, MM, DD, FF);

    // ---- rmsnorm 2 -> final output ----
    red2_kernel<<<1, 256>>>(1024);
    norm_kernel<0><<<2048, 256>>>(out1, mn_a, mn_b, mn_e, out, nullptr, TOT);
}